// round 12
// baseline (speedup 1.0000x reference)
#include <cuda_runtime.h>
#include <cuda_bf16.h>

#define BT_TOK  65536
#define D_INV   512
#define D_EMBV  256
#define K_CODES 1024
#define N_BATCH 16
#define T_SEQ   4096

// ---------------- device scratch ---------------------------------------------
__device__ int           g_code[BT_TOK];
__device__ int           g_cand2[BT_TOK];
__device__ int           g_cnt_r;
__device__ int           g_cnt_f;
__device__ int           g_list_r[BT_TOK];
__device__ int           g_list_f[BT_TOK];
__device__ float         g_c2[K_CODES];
__device__ float         g_loss[N_BATCH];
__device__ __nv_bfloat16 g_wd_h[D_EMBV * D_INV];
__device__ __nv_bfloat16 g_wd_l[D_EMBV * D_INV];
__device__ __nv_bfloat16 g_cb_h[K_CODES * D_EMBV];
__device__ float         g_cbup[K_CODES * D_INV];

// ---------------- helpers -------------------------------------------------------
static __device__ __forceinline__ unsigned smem_u32(const void* p) {
    unsigned a;
    asm("{ .reg .u64 t; cvta.to.shared.u64 t, %1; cvt.u32.u64 %0, t; }"
        : "=r"(a) : "l"(p));
    return a;
}

#define LDSM4(d, addr) \
    asm volatile("ldmatrix.sync.aligned.m8n8.x4.shared.b16 {%0,%1,%2,%3}, [%4];" \
        : "=r"((d)[0]), "=r"((d)[1]), "=r"((d)[2]), "=r"((d)[3]) : "r"(addr))

#define LDSM4B(b0, b1, addr) \
    asm volatile("ldmatrix.sync.aligned.m8n8.x4.shared.b16 {%0,%1,%2,%3}, [%4];" \
        : "=r"((b0)[0]), "=r"((b0)[1]), "=r"((b1)[0]), "=r"((b1)[1]) : "r"(addr))

#define MMA_B16(c, a, b) \
    asm volatile("mma.sync.aligned.m16n8k16.row.col.f32.bf16.bf16.f32 " \
        "{%0,%1,%2,%3},{%4,%5,%6,%7},{%8,%9},{%0,%1,%2,%3};" \
        : "+f"((c)[0]), "+f"((c)[1]), "+f"((c)[2]), "+f"((c)[3]) \
        : "r"((a)[0]), "r"((a)[1]), "r"((a)[2]), "r"((a)[3]), "r"((b)[0]), "r"((b)[1]))

static __device__ __forceinline__ unsigned pack_bf2(float x, float y) {
    __nv_bfloat162 t = __float22bfloat162_rn(make_float2(x, y));
    return *(unsigned*)&t;
}

// 2-way split: v -> hi, lo (each uint2 = 4 bf16)
static __device__ __forceinline__ void split2_f4(float4 v, uint2& h, uint2& l) {
    __nv_bfloat162 h01 = __float22bfloat162_rn(make_float2(v.x, v.y));
    __nv_bfloat162 h23 = __float22bfloat162_rn(make_float2(v.z, v.w));
    float r0 = v.x - __bfloat162float(h01.x);
    float r1 = v.y - __bfloat162float(h01.y);
    float r2 = v.z - __bfloat162float(h23.x);
    float r3 = v.w - __bfloat162float(h23.y);
    h.x = *(unsigned*)&h01; h.y = *(unsigned*)&h23;
    l.x = pack_bf2(r0, r1); l.y = pack_bf2(r2, r3);
}

// top-3 (with indices for top-2) insertion
static __device__ __forceinline__ void ins3(float d, int ix, float& m1, float& m2,
                                            float& m3, int& i1, int& i2) {
    if (d < m1 || (d == m1 && ix < i1)) {
        m3 = m2; m2 = m1; i2 = i1; m1 = d; i1 = ix;
    } else if (d < m2 || (d == m2 && ix < i2)) {
        m3 = m2; m2 = d; i2 = ix;
    } else if (d < m3) {
        m3 = d;
    }
}

// ---------------- prep kernels ---------------------------------------------------
__global__ void k_prep(const float* __restrict__ wd, const float* __restrict__ cb) {
    int i = blockIdx.x * blockDim.x + threadIdx.x;
    if (i < D_EMBV * D_INV) {
        float x = wd[i];
        __nv_bfloat16 h = __float2bfloat16(x);
        g_wd_h[i] = h;
        g_wd_l[i] = __float2bfloat16(x - __bfloat162float(h));
    }
    int j = i - D_EMBV * D_INV;
    if (j >= 0 && j < K_CODES * D_EMBV) {
        g_cb_h[j] = __float2bfloat16(cb[j]);
    }
}
__global__ void k_c2(const float* __restrict__ CB) {
    int k = blockIdx.x * blockDim.x + threadIdx.x;
    if (k < K_CODES) {
        const float* row = CB + (size_t)k * D_EMBV;
        float s = 0.f;
        #pragma unroll 8
        for (int e = 0; e < D_EMBV; e++) s += row[e] * row[e];
        g_c2[k] = s;
    }
}
__global__ void k_zero() {
    if (threadIdx.x < N_BATCH) g_loss[threadIdx.x] = 0.f;
    if (threadIdx.x == 30) g_cnt_r = 0;
    if (threadIdx.x == 31) g_cnt_f = 0;
}

// ---------------- CBup = codebook @ W_up^T (small fp32 SIMT GEMM) ----------------
static __device__ __forceinline__ unsigned long long bcast2(float x) {
    unsigned long long r; asm("mov.b64 %0, {%1, %1};" : "=l"(r) : "f"(x)); return r;
}
static __device__ __forceinline__ void fma2(unsigned long long& c, unsigned long long a,
                                            unsigned long long b) {
    asm("fma.rn.f32x2 %0, %1, %2, %0;" : "+l"(c) : "l"(a), "l"(b));
}
static __device__ __forceinline__ float2 unpack2(unsigned long long v) {
    float2 f;
    f.x = __uint_as_float((unsigned)(v & 0xffffffffull));
    f.y = __uint_as_float((unsigned)(v >> 32));
    return f;
}
__global__ void k_cbup(const float* __restrict__ A, const float* __restrict__ W) {
    __shared__ __align__(16) float As[32][68];
    __shared__ __align__(16) float Bs[32][68];
    const int m0 = blockIdx.x * 64, n0 = blockIdx.y * 64;
    const int tid = threadIdx.x, tx = tid & 15, ty = tid >> 4;
    unsigned long long acc[4][2];
    #pragma unroll
    for (int i = 0; i < 4; i++) { acc[i][0] = 0ull; acc[i][1] = 0ull; }
    for (int kk = 0; kk < D_EMBV; kk += 32) {
        #pragma unroll
        for (int i = 0; i < 8; i++) {
            int idx = tid + i * 256, r = idx >> 5, c = idx & 31;
            As[c][r] = A[(size_t)(m0 + r) * D_EMBV + kk + c];
            Bs[c][r] = W[(size_t)(n0 + r) * D_EMBV + kk + c];
        }
        __syncthreads();
        #pragma unroll
        for (int k = 0; k < 32; k++) {
            float4 av = *(const float4*)&As[k][ty * 4];
            ulonglong2 bv = *(const ulonglong2*)&Bs[k][tx * 4];
            unsigned long long a0 = bcast2(av.x), a1 = bcast2(av.y);
            unsigned long long a2 = bcast2(av.z), a3 = bcast2(av.w);
            fma2(acc[0][0], a0, bv.x); fma2(acc[0][1], a0, bv.y);
            fma2(acc[1][0], a1, bv.x); fma2(acc[1][1], a1, bv.y);
            fma2(acc[2][0], a2, bv.x); fma2(acc[2][1], a2, bv.y);
            fma2(acc[3][0], a3, bv.x); fma2(acc[3][1], a3, bv.y);
        }
        __syncthreads();
    }
    #pragma unroll
    for (int i = 0; i < 4; i++) {
        float2 p0 = unpack2(acc[i][0]), p1 = unpack2(acc[i][1]);
        *(float4*)&g_cbup[(size_t)(m0 + ty * 4 + i) * D_INV + n0 + tx * 4] =
            make_float4(p0.x, p0.y, p1.x, p1.y);
    }
}

// ---------------- k_down: zed = z_e @ Wd^T (2-way split, 3-pass HMMA) ------------
// buffer (40960B): Ah@0 Al@10240 Bh@20480 Bl@30720; x2 buffers. rows 80B.
#define KD_BUF  40960
#define KD_SMEM 81920
__global__ void __launch_bounds__(256, 1) k_down(const float* __restrict__ A,
                                                 float* __restrict__ C) {
    extern __shared__ __align__(16) char sm[];
    const unsigned sb = smem_u32(sm);
    const int tid = threadIdx.x, lane = tid & 31, wid = tid >> 5;
    const int wr = wid >> 1, wc = wid & 1;
    const int m0 = blockIdx.x * 128, n0 = blockIdx.y * 128;

    float acc[2][8][4];
    #pragma unroll
    for (int mi = 0; mi < 2; mi++)
        #pragma unroll
        for (int ni = 0; ni < 8; ni++)
            #pragma unroll
            for (int q = 0; q < 4; q++) acc[mi][ni][q] = 0.f;

    float4 areg[4];
    uint4  bh[2], bl[2];

    #pragma unroll
    for (int i = 0; i < 4; i++) {
        int j = tid + i * 256, r = j >> 3, c4 = j & 7;
        areg[i] = *(const float4*)&A[(size_t)(m0 + r) * D_INV + c4 * 4];
    }
    #pragma unroll
    for (int i = 0; i < 2; i++) {
        int j = tid + i * 256, r = j >> 2, c = j & 3;
        size_t src = (size_t)(n0 + r) * D_INV + c * 8;
        bh[i] = *(const uint4*)&g_wd_h[src];
        bl[i] = *(const uint4*)&g_wd_l[src];
    }
    {
        char* base = sm;
        #pragma unroll
        for (int i = 0; i < 4; i++) {
            int j = tid + i * 256, r = j >> 3, c4 = j & 7;
            uint2 h, l; split2_f4(areg[i], h, l);
            unsigned off = r * 80 + c4 * 8;
            *(uint2*)(base + off) = h;
            *(uint2*)(base + 10240 + off) = l;
        }
        #pragma unroll
        for (int i = 0; i < 2; i++) {
            int j = tid + i * 256, r = j >> 2, c = j & 3;
            unsigned off = r * 80 + c * 16;
            *(uint4*)(base + 20480 + off) = bh[i];
            *(uint4*)(base + 30720 + off) = bl[i];
        }
    }
    __syncthreads();

    #pragma unroll 1
    for (int ch = 0; ch < 16; ch++) {
        int nxt = ch + 1;
        if (nxt < 16) {
            #pragma unroll
            for (int i = 0; i < 4; i++) {
                int j = tid + i * 256, r = j >> 3, c4 = j & 7;
                areg[i] = *(const float4*)&A[(size_t)(m0 + r) * D_INV + nxt * 32 + c4 * 4];
            }
            #pragma unroll
            for (int i = 0; i < 2; i++) {
                int j = tid + i * 256, r = j >> 2, c = j & 3;
                size_t src = (size_t)(n0 + r) * D_INV + nxt * 32 + c * 8;
                bh[i] = *(const uint4*)&g_wd_h[src];
                bl[i] = *(const uint4*)&g_wd_l[src];
            }
        }
        {
            unsigned bufb = sb + (ch & 1) * KD_BUF;
            #pragma unroll
            for (int s = 0; s < 2; s++) {
                unsigned a_h[2][4], a_l[2][4];
                #pragma unroll
                for (int mi = 0; mi < 2; mi++) {
                    unsigned off = (wr * 32 + mi * 16 + (lane & 15)) * 80 +
                                   ((lane >> 4) << 4) + s * 32;
                    LDSM4(a_h[mi], bufb + off);
                    LDSM4(a_l[mi], bufb + 10240 + off);
                }
                #pragma unroll
                for (int nh = 0; nh < 2; nh++) {
                    unsigned b_h[4][2], b_l[4][2];
                    #pragma unroll
                    for (int p = 0; p < 2; p++) {
                        int np = nh * 2 + p;
                        unsigned off = (wc * 64 + np * 16 + (lane & 7) +
                                        ((lane >> 4) << 3)) * 80 +
                                       (((lane >> 3) & 1) << 4) + s * 32;
                        LDSM4B(b_h[p * 2], b_h[p * 2 + 1], bufb + 20480 + off);
                        LDSM4B(b_l[p * 2], b_l[p * 2 + 1], bufb + 30720 + off);
                    }
                    #pragma unroll
                    for (int mi = 0; mi < 2; mi++)
                        #pragma unroll
                        for (int k = 0; k < 4; k++)
                            MMA_B16(acc[mi][nh * 4 + k], a_h[mi], b_h[k]);
                    #pragma unroll
                    for (int mi = 0; mi < 2; mi++)
                        #pragma unroll
                        for (int k = 0; k < 4; k++)
                            MMA_B16(acc[mi][nh * 4 + k], a_l[mi], b_h[k]);
                    #pragma unroll
                    for (int mi = 0; mi < 2; mi++)
                        #pragma unroll
                        for (int k = 0; k < 4; k++)
                            MMA_B16(acc[mi][nh * 4 + k], a_h[mi], b_l[k]);
                }
            }
        }
        if (nxt < 16) {
            char* base = sm + (nxt & 1) * KD_BUF;
            #pragma unroll
            for (int i = 0; i < 4; i++) {
                int j = tid + i * 256, r = j >> 3, c4 = j & 7;
                uint2 h, l; split2_f4(areg[i], h, l);
                unsigned off = r * 80 + c4 * 8;
                *(uint2*)(base + off) = h;
                *(uint2*)(base + 10240 + off) = l;
            }
            #pragma unroll
            for (int i = 0; i < 2; i++) {
                int j = tid + i * 256, r = j >> 2, c = j & 3;
                unsigned off = r * 80 + c * 16;
                *(uint4*)(base + 20480 + off) = bh[i];
                *(uint4*)(base + 30720 + off) = bl[i];
            }
        }
        __syncthreads();
    }
    #pragma unroll
    for (int mi = 0; mi < 2; mi++)
        #pragma unroll
        for (int h = 0; h < 2; h++) {
            int row = m0 + wr * 32 + mi * 16 + h * 8 + (lane >> 2);
            #pragma unroll
            for (int ni = 0; ni < 8; ni++) {
                int col = n0 + wc * 64 + ni * 8 + 2 * (lane & 3);
                *(float2*)&C[(size_t)row * D_EMBV + col] =
                    make_float2(acc[mi][ni][h * 2], acc[mi][ni][h * 2 + 1]);
            }
        }
}

// ---------------- k_dist: 2-pass bf16 dist GEMM + guarded top-3 ------------------
// d = c2 - 2*(z_h + z_l)·c_h  (exact in split arithmetic up to fp32 accum)
// smem: Ah chunks 0..7 @0 (81920) | Al @81920 (81920) | Bh bufs @163840 (2*10240)
// red @184320: m1,m2,m3 (3KB) + i1,i2 (2KB) -> 189440 total
#define DS_AL   81920
#define DS_BB   163840
#define DS_RED  184320
#define DS_SMEM 189440
#define DS_WIN  0.5f
__global__ void __launch_bounds__(256, 1) k_dist(const float* __restrict__ Z,
                                                 float* __restrict__ code_f) {
    extern __shared__ __align__(16) char sm[];
    const unsigned sb = smem_u32(sm);
    const int tid = threadIdx.x, lane = tid & 31, wid = tid >> 5;
    const int wr = wid >> 1, wc = wid & 1;
    const int m0 = blockIdx.x * 128;

    // resident A: split zed[m0..+128, 0..256) into 8 chunk tiles (hi/lo)
    #pragma unroll 4
    for (int i = 0; i < 32; i++) {
        int j = tid + i * 256, r = j >> 6, col4 = j & 63;
        int ch = col4 >> 3, c4 = col4 & 7;
        float4 v = *(const float4*)&Z[(size_t)(m0 + r) * D_EMBV + col4 * 4];
        uint2 h, l; split2_f4(v, h, l);
        unsigned off = ch * 10240 + r * 80 + c4 * 8;
        *(uint2*)(sm + off) = h;
        *(uint2*)(sm + DS_AL + off) = l;
    }

    float acc[2][8][4];
    #pragma unroll
    for (int mi = 0; mi < 2; mi++)
        #pragma unroll
        for (int ni = 0; ni < 8; ni++)
            #pragma unroll
            for (int q = 0; q < 4; q++) acc[mi][ni][q] = 0.f;

    float t1[4], t2[4], t3[4]; int ti1[4], ti2[4];
    #pragma unroll
    for (int s = 0; s < 4; s++) {
        t1[s] = 3.4e38f; t2[s] = 3.4e38f; t3[s] = 3.4e38f;
        ti1[s] = 0x7fffffff; ti2[s] = 0x7fffffff;
    }

    uint4 pbh[2];
    #pragma unroll
    for (int i = 0; i < 2; i++) {
        int j = tid + i * 256, r = j >> 2, c = j & 3;
        pbh[i] = *(const uint4*)&g_cb_h[(size_t)r * D_EMBV + c * 8];
    }
    {
        char* base = sm + DS_BB;
        #pragma unroll
        for (int i = 0; i < 2; i++) {
            int j = tid + i * 256, r = j >> 2, c = j & 3;
            *(uint4*)(base + r * 80 + c * 16) = pbh[i];
        }
    }
    __syncthreads();

    #pragma unroll 1
    for (int it = 0; it < 64; it++) {
        int nt = it >> 3, kc = it & 7;
        int nxt = it + 1;
        if (nxt < 64) {
            int nnt = nxt >> 3, nkc = nxt & 7;
            #pragma unroll
            for (int i = 0; i < 2; i++) {
                int j = tid + i * 256, r = j >> 2, c = j & 3;
                pbh[i] = *(const uint4*)&g_cb_h[(size_t)(nnt * 128 + r) * D_EMBV +
                                                nkc * 32 + c * 8];
            }
        }
        {
            unsigned abase = sb + kc * 10240;
            unsigned bbase = sb + DS_BB + (it & 1) * 10240;
            #pragma unroll
            for (int s = 0; s < 2; s++) {
                unsigned a_h[2][4], a_l[2][4];
                #pragma unroll
                for (int mi = 0; mi < 2; mi++) {
                    unsigned off = (wr * 32 + mi * 16 + (lane & 15)) * 80 +
                                   ((lane >> 4) << 4) + s * 32;
                    LDSM4(a_h[mi], abase + off);
                    LDSM4(a_l[mi], abase + DS_AL + off);
                }
                #pragma unroll
                for (int nh = 0; nh < 2; nh++) {
                    unsigned b_h[4][2];
                    #pragma unroll
                    for (int p = 0; p < 2; p++) {
                        int np = nh * 2 + p;
                        unsigned off = (wc * 64 + np * 16 + (lane & 7) +
                                        ((lane >> 4) << 3)) * 80 +
                                       (((lane >> 3) & 1) << 4) + s * 32;
                        LDSM4B(b_h[p * 2], b_h[p * 2 + 1], bbase + off);
                    }
                    // 2 passes: (a_h + a_l)·b_h
                    #pragma unroll
                    for (int mi = 0; mi < 2; mi++)
                        #pragma unroll
                        for (int k = 0; k < 4; k++)
                            MMA_B16(acc[mi][nh * 4 + k], a_h[mi], b_h[k]);
                    #pragma unroll
                    for (int mi = 0; mi < 2; mi++)
                        #pragma unroll
                        for (int k = 0; k < 4; k++)
                            MMA_B16(acc[mi][nh * 4 + k], a_l[mi], b_h[k]);
                }
            }
        }
        if (kc == 7) {
            #pragma unroll
            for (int ni = 0; ni < 8; ni++)
                #pragma unroll
                for (int cc = 0; cc < 2; cc++) {
                    int g = nt * 128 + wc * 64 + ni * 8 + 2 * (lane & 3) + cc;
                    float c2v = __ldg(&g_c2[g]);
                    #pragma unroll
                    for (int mi = 0; mi < 2; mi++)
                        #pragma unroll
                        for (int h = 0; h < 2; h++) {
                            int slot = mi * 2 + h;
                            float d = c2v - 2.f * acc[mi][ni][h * 2 + cc];
                            if (d < t3[slot])
                                ins3(d, g, t1[slot], t2[slot], t3[slot],
                                     ti1[slot], ti2[slot]);
                        }
                }
            #pragma unroll
            for (int mi = 0; mi < 2; mi++)
                #pragma unroll
                for (int ni = 0; ni < 8; ni++)
                    #pragma unroll
                    for (int q = 0; q < 4; q++) acc[mi][ni][q] = 0.f;
        }
        if (nxt < 64) {
            char* base = sm + DS_BB + (nxt & 1) * 10240;
            #pragma unroll
            for (int i = 0; i < 2; i++) {
                int j = tid + i * 256, r = j >> 2, c = j & 3;
                *(uint4*)(base + r * 80 + c * 16) = pbh[i];
            }
        }
        __syncthreads();
    }

    // quad-shuffle merge of top-3 lists (lanes 4k..4k+3 share rows)
    #pragma unroll
    for (int s = 0; s < 4; s++) {
        #pragma unroll
        for (int off = 1; off <= 2; off <<= 1) {
            float om1 = __shfl_xor_sync(0xffffffffu, t1[s], off);
            float om2 = __shfl_xor_sync(0xffffffffu, t2[s], off);
            float om3 = __shfl_xor_sync(0xffffffffu, t3[s], off);
            int   oi1 = __shfl_xor_sync(0xffffffffu, ti1[s], off);
            int   oi2 = __shfl_xor_sync(0xffffffffu, ti2[s], off);
            ins3(om1, oi1, t1[s], t2[s], t3[s], ti1[s], ti2[s]);
            ins3(om2, oi2, t1[s], t2[s], t3[s], ti1[s], ti2[s]);
            ins3(om3, 0x7fffffff, t1[s], t2[s], t3[s], ti1[s], ti2[s]);
        }
    }
    float* red_m1 = (float*)(sm + DS_RED);
    float* red_m2 = (float*)(sm + DS_RED + 1024);
    float* red_m3 = (float*)(sm + DS_RED + 2048);
    int*   red_i1 = (int*)(sm + DS_RED + 3072);
    int*   red_i2 = (int*)(sm + DS_RED + 4096);
    if ((lane & 3) == 0) {
        #pragma unroll
        for (int mi = 0; mi < 2; mi++)
            #pragma unroll
            for (int h = 0; h < 2; h++) {
                int s = mi * 2 + h;
                int row = wr * 32 + mi * 16 + h * 8 + (lane >> 2);
                red_m1[row * 2 + wc] = t1[s];
                red_m2[row * 2 + wc] = t2[s];
                red_m3[row * 2 + wc] = t3[s];
                red_i1[row * 2 + wc] = ti1[s];
                red_i2[row * 2 + wc] = ti2[s];
            }
    }
    __syncthreads();
    if (tid < 128) {
        float m1 = red_m1[tid * 2], m2 = red_m2[tid * 2], m3 = red_m3[tid * 2];
        int   i1 = red_i1[tid * 2], i2 = red_i2[tid * 2];
        ins3(red_m1[tid * 2 + 1], red_i1[tid * 2 + 1], m1, m2, m3, i1, i2);
        ins3(red_m2[tid * 2 + 1], red_i2[tid * 2 + 1], m1, m2, m3, i1, i2);
        ins3(red_m3[tid * 2 + 1], 0x7fffffff, m1, m2, m3, i1, i2);
        int t = m0 + tid;
        g_code[t] = i1;
        code_f[t] = (float)i1;
        if (m3 < m1 + DS_WIN) {
            int pos = atomicAdd(&g_cnt_f, 1);
            g_list_f[pos] = t;
        } else if (m2 < m1 + DS_WIN) {
            int pos = atomicAdd(&g_cnt_r, 1);
            g_list_r[pos] = t;
            g_cand2[t] = i2;
        }
    }
}

// ---------------- exact fp32 2-candidate recheck ----------------------------------
__global__ void k_recheck(const float* __restrict__ Z, const float* __restrict__ CB,
                          float* __restrict__ code_f) {
    int gw = (blockIdx.x * blockDim.x + threadIdx.x) >> 5;
    int lane = threadIdx.x & 31;
    int nw = (gridDim.x * blockDim.x) >> 5;
    int cnt = g_cnt_r;
    for (int i = gw; i < cnt; i += nw) {
        int t = g_list_r[i];
        int a = g_code[t], b = g_cand2[t];
        const float* z  = Z + (size_t)t * D_EMBV;
        const float* ca = CB + (size_t)a * D_EMBV;
        const float* cb = CB + (size_t)b * D_EMBV;
        float sa = 0.f, sb = 0.f;
        #pragma unroll
        for (int k = 0; k < 8; k++) {
            int e = lane + 32 * k;
            float zv = z[e];
            sa += zv * ca[e];
            sb += zv * cb[e];
        }
        #pragma unroll
        for (int o = 16; o > 0; o >>= 1) {
            sa += __shfl_xor_sync(0xffffffffu, sa, o);
            sb += __shfl_xor_sync(0xffffffffu, sb, o);
        }
        if (lane == 0) {
            float da = g_c2[a] - 2.f * sa;
            float db = g_c2[b] - 2.f * sb;
            int best = (db < da || (db == da && b < a)) ? b : a;
            g_code[t] = best;
            code_f[t] = (float)best;
        }
    }
}

// ---------------- exact fp32 full scan for rare ambiguous tokens ------------------
__global__ void k_fullscan(const float* __restrict__ Z, const float* __restrict__ CB,
                           float* __restrict__ code_f) {
    int gw = (blockIdx.x * blockDim.x + threadIdx.x) >> 5;
    int lane = threadIdx.x & 31;
    int nw = (gridDim.x * blockDim.x) >> 5;
    int cnt = g_cnt_f;
    for (int i = gw; i < cnt; i += nw) {
        int t = g_list_f[i];
        const float* z = Z + (size_t)t * D_EMBV;
        float best = 3.4e38f; int bi = K_CODES;
        for (int kk = lane * 32; kk < lane * 32 + 32; kk++) {
            const float* cr = CB + (size_t)kk * D_EMBV;
            float dot = 0.f;
            #pragma unroll 8
            for (int e = 0; e < D_EMBV; e++) dot += z[e] * cr[e];
            float d = g_c2[kk] - 2.f * dot;
            if (d < best) { best = d; bi = kk; }
        }
        #pragma unroll
        for (int o = 16; o > 0; o >>= 1) {
            float od = __shfl_xor_sync(0xffffffffu, best, o);
            int oi = __shfl_xor_sync(0xffffffffu, bi, o);
            if (od < best || (od == best && oi < bi)) { best = od; bi = oi; }
        }
        if (lane == 0) { g_code[t] = bi; code_f[t] = (float)bi; }
    }
}

// ---------------- gather: zq[t] = CBup[code[t]] ----------------------------------
__global__ void k_gather(float* __restrict__ ZQ) {
    int idx = blockIdx.x * blockDim.x + threadIdx.x;
    int t = idx >> 7, j = idx & 127;
    int code = g_code[t];
    ((float4*)ZQ)[(size_t)t * 128 + j] = ((const float4*)g_cbup)[(size_t)code * 128 + j];
}

// ---------------- per-batch VQ losses --------------------------------------------
__global__ void k_loss(const float* __restrict__ Z, const float* __restrict__ CB) {
    int lane = threadIdx.x & 31;
    int t = (blockIdx.x * blockDim.x + threadIdx.x) >> 5;
    int code = g_code[t];
    float s = 0.f;
    #pragma unroll
    for (int i = 0; i < 8; i++) {
        int e = lane + 32 * i;
        float d = Z[(size_t)t * D_EMBV + e] - CB[(size_t)code * D_EMBV + e];
        s += d * d;
    }
    #pragma unroll
    for (int o = 16; o > 0; o >>= 1) s += __shfl_xor_sync(0xffffffffu, s, o);
    if (lane == 0) atomicAdd(&g_loss[t >> 12], s);
}
__global__ void k_finish(float* __restrict__ oc, float* __restrict__ ob) {
    int i = threadIdx.x;
    if (i < N_BATCH) {
        float v = g_loss[i] * (1.0f / ((float)T_SEQ * (float)D_EMBV));
        oc[i] = v; ob[i] = v;
    }
}

// ---------------- launcher --------------------------------------------------------
extern "C" void kernel_launch(void* const* d_in, const int* in_sizes, int n_in,
                              void* d_out, int out_size) {
    const float* z_e    = (const float*)d_in[0];
    const float* cb     = (const float*)d_in[1];
    const float* w_down = (const float*)d_in[2];
    const float* w_up   = (const float*)d_in[3];

    float* out     = (float*)d_out;
    float* zq      = out;
    float* zed     = out + (size_t)BT_TOK * D_INV;
    float* codef   = out + (size_t)BT_TOK * (D_INV + D_EMBV);
    float* lcommit = codef + BT_TOK;
    float* lcb     = lcommit + N_BATCH;

    cudaFuncSetAttribute(k_down, cudaFuncAttributeMaxDynamicSharedMemorySize, KD_SMEM);
    cudaFuncSetAttribute(k_dist, cudaFuncAttributeMaxDynamicSharedMemorySize, DS_SMEM);

    k_prep<<<(D_EMBV * D_INV + K_CODES * D_EMBV + 255) / 256, 256>>>(w_down, cb);
    k_c2<<<(K_CODES + 255) / 256, 256>>>(cb);
    k_zero<<<1, 32>>>();
    k_cbup<<<dim3(K_CODES / 64, D_INV / 64), 256>>>(cb, w_up);
    k_down<<<dim3(BT_TOK / 128, 2), 256, KD_SMEM>>>(z_e, zed);
    k_dist<<<BT_TOK / 128, 256, DS_SMEM>>>(zed, codef);
    k_recheck<<<64, 256>>>(zed, cb, codef);
    k_fullscan<<<64, 256>>>(zed, cb, codef);
    k_gather<<<(BT_TOK * 128) / 256, 256>>>(zq);
    k_loss<<<BT_TOK / 8, 256>>>(zed, cb);
    k_finish<<<1, 32>>>(lcommit, lcb);
}

// round 13
// speedup vs baseline: 1.0342x; 1.0342x over previous
#include <cuda_runtime.h>
#include <cuda_bf16.h>

#define BT_TOK  65536
#define D_INV   512
#define D_EMBV  256
#define K_CODES 1024
#define N_BATCH 16
#define T_SEQ   4096

// ---------------- device scratch ---------------------------------------------
__device__ int           g_code[BT_TOK];
__device__ int           g_cand2[BT_TOK];
__device__ int           g_cnt_r;
__device__ int           g_cnt_f;
__device__ int           g_list_r[BT_TOK];
__device__ int           g_list_f[BT_TOK];
__device__ float         g_c2[K_CODES];
__device__ float         g_loss[N_BATCH];
__device__ __nv_bfloat16 g_wd_h[D_EMBV * D_INV];
__device__ __nv_bfloat16 g_wd_l[D_EMBV * D_INV];
__device__ __nv_bfloat16 g_cb_h[K_CODES * D_EMBV];
__device__ float         g_cbup[K_CODES * D_INV];

// ---------------- helpers -------------------------------------------------------
static __device__ __forceinline__ unsigned smem_u32(const void* p) {
    unsigned a;
    asm("{ .reg .u64 t; cvta.to.shared.u64 t, %1; cvt.u32.u64 %0, t; }"
        : "=r"(a) : "l"(p));
    return a;
}

#define LDSM4(d, addr) \
    asm volatile("ldmatrix.sync.aligned.m8n8.x4.shared.b16 {%0,%1,%2,%3}, [%4];" \
        : "=r"((d)[0]), "=r"((d)[1]), "=r"((d)[2]), "=r"((d)[3]) : "r"(addr))

#define LDSM4B(b0, b1, addr) \
    asm volatile("ldmatrix.sync.aligned.m8n8.x4.shared.b16 {%0,%1,%2,%3}, [%4];" \
        : "=r"((b0)[0]), "=r"((b0)[1]), "=r"((b1)[0]), "=r"((b1)[1]) : "r"(addr))

#define MMA_B16(c, a, b) \
    asm volatile("mma.sync.aligned.m16n8k16.row.col.f32.bf16.bf16.f32 " \
        "{%0,%1,%2,%3},{%4,%5,%6,%7},{%8,%9},{%0,%1,%2,%3};" \
        : "+f"((c)[0]), "+f"((c)[1]), "+f"((c)[2]), "+f"((c)[3]) \
        : "r"((a)[0]), "r"((a)[1]), "r"((a)[2]), "r"((a)[3]), "r"((b)[0]), "r"((b)[1]))

#define CP_ASYNC16(dst, src) \
    asm volatile("cp.async.cg.shared.global [%0], [%1], 16;" \
        :: "r"(dst), "l"(src) : "memory")
#define CP_COMMIT() asm volatile("cp.async.commit_group;" ::: "memory")
#define CP_WAIT(n)  asm volatile("cp.async.wait_group %0;" :: "n"(n) : "memory")

static __device__ __forceinline__ unsigned pack_bf2(float x, float y) {
    __nv_bfloat162 t = __float22bfloat162_rn(make_float2(x, y));
    return *(unsigned*)&t;
}

// 2-way split: v -> hi, lo (each uint2 = 4 bf16)
static __device__ __forceinline__ void split2_f4(float4 v, uint2& h, uint2& l) {
    __nv_bfloat162 h01 = __float22bfloat162_rn(make_float2(v.x, v.y));
    __nv_bfloat162 h23 = __float22bfloat162_rn(make_float2(v.z, v.w));
    float r0 = v.x - __bfloat162float(h01.x);
    float r1 = v.y - __bfloat162float(h01.y);
    float r2 = v.z - __bfloat162float(h23.x);
    float r3 = v.w - __bfloat162float(h23.y);
    h.x = *(unsigned*)&h01; h.y = *(unsigned*)&h23;
    l.x = pack_bf2(r0, r1); l.y = pack_bf2(r2, r3);
}
static __device__ __forceinline__ uint2 cvt_hi_f4(float4 v) {
    uint2 h;
    h.x = pack_bf2(v.x, v.y);
    h.y = pack_bf2(v.z, v.w);
    return h;
}

// top-3 (with indices for top-2) insertion
static __device__ __forceinline__ void ins3(float d, int ix, float& m1, float& m2,
                                            float& m3, int& i1, int& i2) {
    if (d < m1 || (d == m1 && ix < i1)) {
        m3 = m2; m2 = m1; i2 = i1; m1 = d; i1 = ix;
    } else if (d < m2 || (d == m2 && ix < i2)) {
        m3 = m2; m2 = d; i2 = ix;
    } else if (d < m3) {
        m3 = d;
    }
}

// ---------------- prep kernels ---------------------------------------------------
__global__ void k_prep(const float* __restrict__ wd, const float* __restrict__ cb) {
    int i = blockIdx.x * blockDim.x + threadIdx.x;
    if (i < D_EMBV * D_INV) {
        float x = wd[i];
        __nv_bfloat16 h = __float2bfloat16(x);
        g_wd_h[i] = h;
        g_wd_l[i] = __float2bfloat16(x - __bfloat162float(h));
    }
    int j = i - D_EMBV * D_INV;
    if (j >= 0 && j < K_CODES * D_EMBV) {
        g_cb_h[j] = __float2bfloat16(cb[j]);
    }
}
__global__ void k_c2(const float* __restrict__ CB) {
    int k = blockIdx.x * blockDim.x + threadIdx.x;
    if (k < K_CODES) {
        const float* row = CB + (size_t)k * D_EMBV;
        float s = 0.f;
        #pragma unroll 8
        for (int e = 0; e < D_EMBV; e++) s += row[e] * row[e];
        g_c2[k] = s;
    }
}
__global__ void k_zero() {
    if (threadIdx.x < N_BATCH) g_loss[threadIdx.x] = 0.f;
    if (threadIdx.x == 30) g_cnt_r = 0;
    if (threadIdx.x == 31) g_cnt_f = 0;
}

// ---------------- CBup = codebook @ W_up^T (small fp32 SIMT GEMM) ----------------
static __device__ __forceinline__ unsigned long long bcast2(float x) {
    unsigned long long r; asm("mov.b64 %0, {%1, %1};" : "=l"(r) : "f"(x)); return r;
}
static __device__ __forceinline__ void fma2(unsigned long long& c, unsigned long long a,
                                            unsigned long long b) {
    asm("fma.rn.f32x2 %0, %1, %2, %0;" : "+l"(c) : "l"(a), "l"(b));
}
static __device__ __forceinline__ float2 unpack2(unsigned long long v) {
    float2 f;
    f.x = __uint_as_float((unsigned)(v & 0xffffffffull));
    f.y = __uint_as_float((unsigned)(v >> 32));
    return f;
}
__global__ void k_cbup(const float* __restrict__ A, const float* __restrict__ W) {
    __shared__ __align__(16) float As[32][68];
    __shared__ __align__(16) float Bs[32][68];
    const int m0 = blockIdx.x * 64, n0 = blockIdx.y * 64;
    const int tid = threadIdx.x, tx = tid & 15, ty = tid >> 4;
    unsigned long long acc[4][2];
    #pragma unroll
    for (int i = 0; i < 4; i++) { acc[i][0] = 0ull; acc[i][1] = 0ull; }
    for (int kk = 0; kk < D_EMBV; kk += 32) {
        #pragma unroll
        for (int i = 0; i < 8; i++) {
            int idx = tid + i * 256, r = idx >> 5, c = idx & 31;
            As[c][r] = A[(size_t)(m0 + r) * D_EMBV + kk + c];
            Bs[c][r] = W[(size_t)(n0 + r) * D_EMBV + kk + c];
        }
        __syncthreads();
        #pragma unroll
        for (int k = 0; k < 32; k++) {
            float4 av = *(const float4*)&As[k][ty * 4];
            ulonglong2 bv = *(const ulonglong2*)&Bs[k][tx * 4];
            unsigned long long a0 = bcast2(av.x), a1 = bcast2(av.y);
            unsigned long long a2 = bcast2(av.z), a3 = bcast2(av.w);
            fma2(acc[0][0], a0, bv.x); fma2(acc[0][1], a0, bv.y);
            fma2(acc[1][0], a1, bv.x); fma2(acc[1][1], a1, bv.y);
            fma2(acc[2][0], a2, bv.x); fma2(acc[2][1], a2, bv.y);
            fma2(acc[3][0], a3, bv.x); fma2(acc[3][1], a3, bv.y);
        }
        __syncthreads();
    }
    #pragma unroll
    for (int i = 0; i < 4; i++) {
        float2 p0 = unpack2(acc[i][0]), p1 = unpack2(acc[i][1]);
        *(float4*)&g_cbup[(size_t)(m0 + ty * 4 + i) * D_INV + n0 + tx * 4] =
            make_float4(p0.x, p0.y, p1.x, p1.y);
    }
}

// ---------------- k_down: zed = z_e @ Wd^T (2-way split, 3-pass HMMA) ------------
// buffer (40960B): Ah@0 Al@10240 Bh@20480 Bl@30720; x2 buffers. rows 80B.
#define KD_BUF  40960
#define KD_SMEM 81920
__global__ void __launch_bounds__(256, 1) k_down(const float* __restrict__ A,
                                                 float* __restrict__ C) {
    extern __shared__ __align__(16) char sm[];
    const unsigned sb = smem_u32(sm);
    const int tid = threadIdx.x, lane = tid & 31, wid = tid >> 5;
    const int wr = wid >> 1, wc = wid & 1;
    const int m0 = blockIdx.x * 128, n0 = blockIdx.y * 128;

    float acc[2][8][4];
    #pragma unroll
    for (int mi = 0; mi < 2; mi++)
        #pragma unroll
        for (int ni = 0; ni < 8; ni++)
            #pragma unroll
            for (int q = 0; q < 4; q++) acc[mi][ni][q] = 0.f;

    float4 areg[4];
    uint4  bh[2], bl[2];

    #pragma unroll
    for (int i = 0; i < 4; i++) {
        int j = tid + i * 256, r = j >> 3, c4 = j & 7;
        areg[i] = *(const float4*)&A[(size_t)(m0 + r) * D_INV + c4 * 4];
    }
    #pragma unroll
    for (int i = 0; i < 2; i++) {
        int j = tid + i * 256, r = j >> 2, c = j & 3;
        size_t src = (size_t)(n0 + r) * D_INV + c * 8;
        bh[i] = *(const uint4*)&g_wd_h[src];
        bl[i] = *(const uint4*)&g_wd_l[src];
    }
    {
        char* base = sm;
        #pragma unroll
        for (int i = 0; i < 4; i++) {
            int j = tid + i * 256, r = j >> 3, c4 = j & 7;
            uint2 h, l; split2_f4(areg[i], h, l);
            unsigned off = r * 80 + c4 * 8;
            *(uint2*)(base + off) = h;
            *(uint2*)(base + 10240 + off) = l;
        }
        #pragma unroll
        for (int i = 0; i < 2; i++) {
            int j = tid + i * 256, r = j >> 2, c = j & 3;
            unsigned off = r * 80 + c * 16;
            *(uint4*)(base + 20480 + off) = bh[i];
            *(uint4*)(base + 30720 + off) = bl[i];
        }
    }
    __syncthreads();

    #pragma unroll 1
    for (int ch = 0; ch < 16; ch++) {
        int nxt = ch + 1;
        if (nxt < 16) {
            #pragma unroll
            for (int i = 0; i < 4; i++) {
                int j = tid + i * 256, r = j >> 3, c4 = j & 7;
                areg[i] = *(const float4*)&A[(size_t)(m0 + r) * D_INV + nxt * 32 + c4 * 4];
            }
            #pragma unroll
            for (int i = 0; i < 2; i++) {
                int j = tid + i * 256, r = j >> 2, c = j & 3;
                size_t src = (size_t)(n0 + r) * D_INV + nxt * 32 + c * 8;
                bh[i] = *(const uint4*)&g_wd_h[src];
                bl[i] = *(const uint4*)&g_wd_l[src];
            }
        }
        {
            unsigned bufb = sb + (ch & 1) * KD_BUF;
            #pragma unroll
            for (int s = 0; s < 2; s++) {
                unsigned a_h[2][4], a_l[2][4];
                #pragma unroll
                for (int mi = 0; mi < 2; mi++) {
                    unsigned off = (wr * 32 + mi * 16 + (lane & 15)) * 80 +
                                   ((lane >> 4) << 4) + s * 32;
                    LDSM4(a_h[mi], bufb + off);
                    LDSM4(a_l[mi], bufb + 10240 + off);
                }
                #pragma unroll
                for (int nh = 0; nh < 2; nh++) {
                    unsigned b_h[4][2], b_l[4][2];
                    #pragma unroll
                    for (int p = 0; p < 2; p++) {
                        int np = nh * 2 + p;
                        unsigned off = (wc * 64 + np * 16 + (lane & 7) +
                                        ((lane >> 4) << 3)) * 80 +
                                       (((lane >> 3) & 1) << 4) + s * 32;
                        LDSM4B(b_h[p * 2], b_h[p * 2 + 1], bufb + 20480 + off);
                        LDSM4B(b_l[p * 2], b_l[p * 2 + 1], bufb + 30720 + off);
                    }
                    #pragma unroll
                    for (int mi = 0; mi < 2; mi++)
                        #pragma unroll
                        for (int k = 0; k < 4; k++)
                            MMA_B16(acc[mi][nh * 4 + k], a_h[mi], b_h[k]);
                    #pragma unroll
                    for (int mi = 0; mi < 2; mi++)
                        #pragma unroll
                        for (int k = 0; k < 4; k++)
                            MMA_B16(acc[mi][nh * 4 + k], a_l[mi], b_h[k]);
                    #pragma unroll
                    for (int mi = 0; mi < 2; mi++)
                        #pragma unroll
                        for (int k = 0; k < 4; k++)
                            MMA_B16(acc[mi][nh * 4 + k], a_h[mi], b_l[k]);
                }
            }
        }
        if (nxt < 16) {
            char* base = sm + (nxt & 1) * KD_BUF;
            #pragma unroll
            for (int i = 0; i < 4; i++) {
                int j = tid + i * 256, r = j >> 3, c4 = j & 7;
                uint2 h, l; split2_f4(areg[i], h, l);
                unsigned off = r * 80 + c4 * 8;
                *(uint2*)(base + off) = h;
                *(uint2*)(base + 10240 + off) = l;
            }
            #pragma unroll
            for (int i = 0; i < 2; i++) {
                int j = tid + i * 256, r = j >> 2, c = j & 3;
                unsigned off = r * 80 + c * 16;
                *(uint4*)(base + 20480 + off) = bh[i];
                *(uint4*)(base + 30720 + off) = bl[i];
            }
        }
        __syncthreads();
    }
    #pragma unroll
    for (int mi = 0; mi < 2; mi++)
        #pragma unroll
        for (int h = 0; h < 2; h++) {
            int row = m0 + wr * 32 + mi * 16 + h * 8 + (lane >> 2);
            #pragma unroll
            for (int ni = 0; ni < 8; ni++) {
                int col = n0 + wc * 64 + ni * 8 + 2 * (lane & 3);
                *(float2*)&C[(size_t)row * D_EMBV + col] =
                    make_float2(acc[mi][ni][h * 2], acc[mi][ni][h * 2 + 1]);
            }
        }
}

// ---------------- k_dist: 1-pass bf16, cp.async double-buffered fat tiles --------
// 16 N-tiles of 64 codes x full K=256. B tile = 8 kc sub-tiles of [64r x 32d]
// (80B rows) = 40960B per buffer, 2 buffers.
// smem: Ah chunks 0..7 @0 (81920) | B bufs @81920 (2*40960) | red @163840 (5120)
#define DS_BB   81920
#define DS_RED  163840
#define DS_SMEM 168960
#define DS_WIN  1.0f
__global__ void __launch_bounds__(256, 1) k_dist(const float* __restrict__ Z,
                                                 float* __restrict__ code_f) {
    extern __shared__ __align__(16) char sm[];
    const unsigned sb = smem_u32(sm);
    const int tid = threadIdx.x, lane = tid & 31, wid = tid >> 5;
    const int wr = wid >> 1, wc = wid & 1;
    const int m0 = blockIdx.x * 128;

    // resident A (hi only): zed[m0..+128, 0..256) in 8 k-chunk tiles
    #pragma unroll 4
    for (int i = 0; i < 32; i++) {
        int j = tid + i * 256, r = j >> 6, col4 = j & 63;
        int ch = col4 >> 3, c4 = col4 & 7;
        float4 v = *(const float4*)&Z[(size_t)(m0 + r) * D_EMBV + col4 * 4];
        *(uint2*)(sm + ch * 10240 + r * 80 + c4 * 8) = cvt_hi_f4(v);
    }

    float acc[2][4][4];
    #pragma unroll
    for (int mi = 0; mi < 2; mi++)
        #pragma unroll
        for (int nj = 0; nj < 4; nj++)
            #pragma unroll
            for (int q = 0; q < 4; q++) acc[mi][nj][q] = 0.f;

    float t1[4], t2[4], t3[4]; int ti1[4], ti2[4];
    #pragma unroll
    for (int s = 0; s < 4; s++) {
        t1[s] = 3.4e38f; t2[s] = 3.4e38f; t3[s] = 3.4e38f;
        ti1[s] = 0x7fffffff; ti2[s] = 0x7fffffff;
    }

    // async load of B tile nt into buffer buf (2048 16B units, 8 per thread)
    auto load_b = [&](int nt, int buf) {
        unsigned dbase = sb + DS_BB + buf * 40960;
        const __nv_bfloat16* src0 = g_cb_h + (size_t)nt * 64 * D_EMBV;
        #pragma unroll
        for (int i = 0; i < 8; i++) {
            int u = tid + i * 256;
            int kc = u >> 8, rem = u & 255;
            int r = rem >> 2, c = rem & 3;
            unsigned dst = dbase + kc * 5120 + r * 80 + c * 16;
            const __nv_bfloat16* src = src0 + (size_t)r * D_EMBV + kc * 32 + c * 8;
            CP_ASYNC16(dst, src);
        }
        CP_COMMIT();
    };

    load_b(0, 0);
    __syncthreads();   // A-resident stores also complete before first compute

    #pragma unroll 1
    for (int nt = 0; nt < 16; nt++) {
        if (nt + 1 < 16) load_b(nt + 1, (nt + 1) & 1);
        if (nt + 1 < 16) { CP_WAIT(1); } else { CP_WAIT(0); }
        __syncthreads();

        unsigned bbase = sb + DS_BB + (nt & 1) * 40960;
        #pragma unroll 1
        for (int kc = 0; kc < 8; kc++) {
            unsigned abase = sb + kc * 10240;
            unsigned bsub = bbase + kc * 5120;
            #pragma unroll
            for (int s = 0; s < 2; s++) {
                unsigned a_h[2][4];
                #pragma unroll
                for (int mi = 0; mi < 2; mi++) {
                    unsigned off = (wr * 32 + mi * 16 + (lane & 15)) * 80 +
                                   ((lane >> 4) << 4) + s * 32;
                    LDSM4(a_h[mi], abase + off);
                }
                unsigned b_h[4][2];
                #pragma unroll
                for (int p = 0; p < 2; p++) {
                    unsigned off = (wc * 32 + p * 16 + (lane & 7) +
                                    ((lane >> 4) << 3)) * 80 +
                                   (((lane >> 3) & 1) << 4) + s * 32;
                    LDSM4B(b_h[p * 2], b_h[p * 2 + 1], bsub + off);
                }
                #pragma unroll
                for (int mi = 0; mi < 2; mi++)
                    #pragma unroll
                    for (int k = 0; k < 4; k++)
                        MMA_B16(acc[mi][k], a_h[mi], b_h[k]);
            }
        }
        // epilogue for this 64-code tile
        #pragma unroll
        for (int nj = 0; nj < 4; nj++)
            #pragma unroll
            for (int cc = 0; cc < 2; cc++) {
                int g = nt * 64 + wc * 32 + nj * 8 + 2 * (lane & 3) + cc;
                float c2v = __ldg(&g_c2[g]);
                #pragma unroll
                for (int mi = 0; mi < 2; mi++)
                    #pragma unroll
                    for (int h = 0; h < 2; h++) {
                        int slot = mi * 2 + h;
                        float d = c2v - 2.f * acc[mi][nj][h * 2 + cc];
                        if (d < t3[slot])
                            ins3(d, g, t1[slot], t2[slot], t3[slot],
                                 ti1[slot], ti2[slot]);
                    }
            }
        #pragma unroll
        for (int mi = 0; mi < 2; mi++)
            #pragma unroll
            for (int nj = 0; nj < 4; nj++)
                #pragma unroll
                for (int q = 0; q < 4; q++) acc[mi][nj][q] = 0.f;
        __syncthreads();   // protect buffer (nt&1) before it is re-filled at nt+2
    }

    // quad-shuffle merge of top-3 lists (lanes 4k..4k+3 share rows)
    #pragma unroll
    for (int s = 0; s < 4; s++) {
        #pragma unroll
        for (int off = 1; off <= 2; off <<= 1) {
            float om1 = __shfl_xor_sync(0xffffffffu, t1[s], off);
            float om2 = __shfl_xor_sync(0xffffffffu, t2[s], off);
            float om3 = __shfl_xor_sync(0xffffffffu, t3[s], off);
            int   oi1 = __shfl_xor_sync(0xffffffffu, ti1[s], off);
            int   oi2 = __shfl_xor_sync(0xffffffffu, ti2[s], off);
            ins3(om1, oi1, t1[s], t2[s], t3[s], ti1[s], ti2[s]);
            ins3(om2, oi2, t1[s], t2[s], t3[s], ti1[s], ti2[s]);
            ins3(om3, 0x7fffffff, t1[s], t2[s], t3[s], ti1[s], ti2[s]);
        }
    }
    float* red_m1 = (float*)(sm + DS_RED);
    float* red_m2 = (float*)(sm + DS_RED + 1024);
    float* red_m3 = (float*)(sm + DS_RED + 2048);
    int*   red_i1 = (int*)(sm + DS_RED + 3072);
    int*   red_i2 = (int*)(sm + DS_RED + 4096);
    if ((lane & 3) == 0) {
        #pragma unroll
        for (int mi = 0; mi < 2; mi++)
            #pragma unroll
            for (int h = 0; h < 2; h++) {
                int s = mi * 2 + h;
                int row = wr * 32 + mi * 16 + h * 8 + (lane >> 2);
                red_m1[row * 2 + wc] = t1[s];
                red_m2[row * 2 + wc] = t2[s];
                red_m3[row * 2 + wc] = t3[s];
                red_i1[row * 2 + wc] = ti1[s];
                red_i2[row * 2 + wc] = ti2[s];
            }
    }
    __syncthreads();
    if (tid < 128) {
        float m1 = red_m1[tid * 2], m2 = red_m2[tid * 2], m3 = red_m3[tid * 2];
        int   i1 = red_i1[tid * 2], i2 = red_i2[tid * 2];
        ins3(red_m1[tid * 2 + 1], red_i1[tid * 2 + 1], m1, m2, m3, i1, i2);
        ins3(red_m2[tid * 2 + 1], red_i2[tid * 2 + 1], m1, m2, m3, i1, i2);
        ins3(red_m3[tid * 2 + 1], 0x7fffffff, m1, m2, m3, i1, i2);
        int t = m0 + tid;
        g_code[t] = i1;
        code_f[t] = (float)i1;
        if (m3 < m1 + DS_WIN) {
            int pos = atomicAdd(&g_cnt_f, 1);
            g_list_f[pos] = t;
        } else if (m2 < m1 + DS_WIN) {
            int pos = atomicAdd(&g_cnt_r, 1);
            g_list_r[pos] = t;
            g_cand2[t] = i2;
        }
    }
}

// ---------------- exact fp32 2-candidate recheck ----------------------------------
__global__ void k_recheck(const float* __restrict__ Z, const float* __restrict__ CB,
                          float* __restrict__ code_f) {
    int gw = (blockIdx.x * blockDim.x + threadIdx.x) >> 5;
    int lane = threadIdx.x & 31;
    int nw = (gridDim.x * blockDim.x) >> 5;
    int cnt = g_cnt_r;
    for (int i = gw; i < cnt; i += nw) {
        int t = g_list_r[i];
        int a = g_code[t], b = g_cand2[t];
        const float* z  = Z + (size_t)t * D_EMBV;
        const float* ca = CB + (size_t)a * D_EMBV;
        const float* cb = CB + (size_t)b * D_EMBV;
        float sa = 0.f, sb = 0.f;
        #pragma unroll
        for (int k = 0; k < 8; k++) {
            int e = lane + 32 * k;
            float zv = z[e];
            sa += zv * ca[e];
            sb += zv * cb[e];
        }
        #pragma unroll
        for (int o = 16; o > 0; o >>= 1) {
            sa += __shfl_xor_sync(0xffffffffu, sa, o);
            sb += __shfl_xor_sync(0xffffffffu, sb, o);
        }
        if (lane == 0) {
            float da = g_c2[a] - 2.f * sa;
            float db = g_c2[b] - 2.f * sb;
            int best = (db < da || (db == da && b < a)) ? b : a;
            g_code[t] = best;
            code_f[t] = (float)best;
        }
    }
}

// ---------------- exact fp32 full scan for rare ambiguous tokens ------------------
__global__ void k_fullscan(const float* __restrict__ Z, const float* __restrict__ CB,
                           float* __restrict__ code_f) {
    int gw = (blockIdx.x * blockDim.x + threadIdx.x) >> 5;
    int lane = threadIdx.x & 31;
    int nw = (gridDim.x * blockDim.x) >> 5;
    int cnt = g_cnt_f;
    for (int i = gw; i < cnt; i += nw) {
        int t = g_list_f[i];
        const float* z = Z + (size_t)t * D_EMBV;
        float best = 3.4e38f; int bi = K_CODES;
        for (int kk = lane * 32; kk < lane * 32 + 32; kk++) {
            const float* cr = CB + (size_t)kk * D_EMBV;
            float dot = 0.f;
            #pragma unroll 8
            for (int e = 0; e < D_EMBV; e++) dot += z[e] * cr[e];
            float d = g_c2[kk] - 2.f * dot;
            if (d < best) { best = d; bi = kk; }
        }
        #pragma unroll
        for (int o = 16; o > 0; o >>= 1) {
            float od = __shfl_xor_sync(0xffffffffu, best, o);
            int oi = __shfl_xor_sync(0xffffffffu, bi, o);
            if (od < best || (od == best && oi < bi)) { best = od; bi = oi; }
        }
        if (lane == 0) { g_code[t] = bi; code_f[t] = (float)bi; }
    }
}

// ---------------- gather: zq[t] = CBup[code[t]] ----------------------------------
__global__ void k_gather(float* __restrict__ ZQ) {
    int idx = blockIdx.x * blockDim.x + threadIdx.x;
    int t = idx >> 7, j = idx & 127;
    int code = g_code[t];
    ((float4*)ZQ)[(size_t)t * 128 + j] = ((const float4*)g_cbup)[(size_t)code * 128 + j];
}

// ---------------- per-batch VQ losses --------------------------------------------
__global__ void k_loss(const float* __restrict__ Z, const float* __restrict__ CB) {
    int lane = threadIdx.x & 31;
    int t = (blockIdx.x * blockDim.x + threadIdx.x) >> 5;
    int code = g_code[t];
    float s = 0.f;
    #pragma unroll
    for (int i = 0; i < 8; i++) {
        int e = lane + 32 * i;
        float d = Z[(size_t)t * D_EMBV + e] - CB[(size_t)code * D_EMBV + e];
        s += d * d;
    }
    #pragma unroll
    for (int o = 16; o > 0; o >>= 1) s += __shfl_xor_sync(0xffffffffu, s, o);
    if (lane == 0) atomicAdd(&g_loss[t >> 12], s);
}
__global__ void k_finish(float* __restrict__ oc, float* __restrict__ ob) {
    int i = threadIdx.x;
    if (i < N_BATCH) {
        float v = g_loss[i] * (1.0f / ((float)T_SEQ * (float)D_EMBV));
        oc[i] = v; ob[i] = v;
    }
}

// ---------------- launcher --------------------------------------------------------
extern "C" void kernel_launch(void* const* d_in, const int* in_sizes, int n_in,
                              void* d_out, int out_size) {
    const float* z_e    = (const float*)d_in[0];
    const float* cb     = (const float*)d_in[1];
    const float* w_down = (const float*)d_in[2];
    const float* w_up   = (const float*)d_in[3];

    float* out     = (float*)d_out;
    float* zq      = out;
    float* zed     = out + (size_t)BT_TOK * D_INV;
    float* codef   = out + (size_t)BT_TOK * (D_INV + D_EMBV);
    float* lcommit = codef + BT_TOK;
    float* lcb     = lcommit + N_BATCH;

    cudaFuncSetAttribute(k_down, cudaFuncAttributeMaxDynamicSharedMemorySize, KD_SMEM);
    cudaFuncSetAttribute(k_dist, cudaFuncAttributeMaxDynamicSharedMemorySize, DS_SMEM);

    k_prep<<<(D_EMBV * D_INV + K_CODES * D_EMBV + 255) / 256, 256>>>(w_down, cb);
    k_c2<<<(K_CODES + 255) / 256, 256>>>(cb);
    k_zero<<<1, 32>>>();
    k_cbup<<<dim3(K_CODES / 64, D_INV / 64), 256>>>(cb, w_up);
    k_down<<<dim3(BT_TOK / 128, 2), 256, KD_SMEM>>>(z_e, zed);
    k_dist<<<BT_TOK / 128, 256, DS_SMEM>>>(zed, codef);
    k_recheck<<<64, 256>>>(zed, cb, codef);
    k_fullscan<<<64, 256>>>(zed, cb, codef);
    k_gather<<<(BT_TOK * 128) / 256, 256>>>(zq);
    k_loss<<<BT_TOK / 8, 256>>>(zed, cb);
    k_finish<<<1, 32>>>(lcommit, lcb);
}

// round 14
// speedup vs baseline: 1.3864x; 1.3405x over previous
#include <cuda_runtime.h>
#include <cuda_bf16.h>

#define BT_TOK  65536
#define D_INV   512
#define D_EMBV  256
#define K_CODES 1024
#define N_BATCH 16
#define T_SEQ   4096

// ---------------- device scratch ---------------------------------------------
__device__ int           g_code[BT_TOK];
__device__ int           g_flag[BT_TOK];
__device__ float         g_c2[K_CODES];
__device__ float         g_loss[N_BATCH];
__device__ __nv_bfloat16 g_wd_h[D_EMBV * D_INV];
__device__ __nv_bfloat16 g_wd_l[D_EMBV * D_INV];
__device__ __nv_bfloat16 g_cb_h[K_CODES * D_EMBV];
__device__ __nv_bfloat16 g_cb_l[K_CODES * D_EMBV];
__device__ float         g_cbup[K_CODES * D_INV];

// ---------------- helpers -------------------------------------------------------
static __device__ __forceinline__ unsigned smem_u32(const void* p) {
    unsigned a;
    asm("{ .reg .u64 t; cvta.to.shared.u64 t, %1; cvt.u32.u64 %0, t; }"
        : "=r"(a) : "l"(p));
    return a;
}

#define LDSM4(d, addr) \
    asm volatile("ldmatrix.sync.aligned.m8n8.x4.shared.b16 {%0,%1,%2,%3}, [%4];" \
        : "=r"((d)[0]), "=r"((d)[1]), "=r"((d)[2]), "=r"((d)[3]) : "r"(addr))

#define LDSM4B(b0, b1, addr) \
    asm volatile("ldmatrix.sync.aligned.m8n8.x4.shared.b16 {%0,%1,%2,%3}, [%4];" \
        : "=r"((b0)[0]), "=r"((b0)[1]), "=r"((b1)[0]), "=r"((b1)[1]) : "r"(addr))

#define MMA_B16(c, a, b) \
    asm volatile("mma.sync.aligned.m16n8k16.row.col.f32.bf16.bf16.f32 " \
        "{%0,%1,%2,%3},{%4,%5,%6,%7},{%8,%9},{%0,%1,%2,%3};" \
        : "+f"((c)[0]), "+f"((c)[1]), "+f"((c)[2]), "+f"((c)[3]) \
        : "r"((a)[0]), "r"((a)[1]), "r"((a)[2]), "r"((a)[3]), "r"((b)[0]), "r"((b)[1]))

#define CP_ASYNC16(dst, src) \
    asm volatile("cp.async.cg.shared.global [%0], [%1], 16;" \
        :: "r"(dst), "l"(src) : "memory")
#define CP_COMMIT() asm volatile("cp.async.commit_group;" ::: "memory")
#define CP_WAIT0()  asm volatile("cp.async.wait_group 0;" ::: "memory")

static __device__ __forceinline__ unsigned pack_bf2(float x, float y) {
    __nv_bfloat162 t = __float22bfloat162_rn(make_float2(x, y));
    return *(unsigned*)&t;
}

// 2-way split: v -> hi, lo  (each uint2 = 4 bf16)
static __device__ __forceinline__ void split2_f4(float4 v, uint2& h, uint2& l) {
    __nv_bfloat162 h01 = __float22bfloat162_rn(make_float2(v.x, v.y));
    __nv_bfloat162 h23 = __float22bfloat162_rn(make_float2(v.z, v.w));
    float r0 = v.x - __bfloat162float(h01.x);
    float r1 = v.y - __bfloat162float(h01.y);
    float r2 = v.z - __bfloat162float(h23.x);
    float r3 = v.w - __bfloat162float(h23.y);
    h.x = *(unsigned*)&h01; h.y = *(unsigned*)&h23;
    l.x = pack_bf2(r0, r1); l.y = pack_bf2(r2, r3);
}

// ---------------- prep kernels ---------------------------------------------------
__global__ void k_prep(const float* __restrict__ wd, const float* __restrict__ cb) {
    int i = blockIdx.x * blockDim.x + threadIdx.x;
    if (i < D_EMBV * D_INV) {
        float x = wd[i];
        __nv_bfloat16 h = __float2bfloat16(x);
        g_wd_h[i] = h;
        g_wd_l[i] = __float2bfloat16(x - __bfloat162float(h));
    }
    int j = i - D_EMBV * D_INV;
    if (j >= 0 && j < K_CODES * D_EMBV) {
        float x = cb[j];
        __nv_bfloat16 h = __float2bfloat16(x);
        g_cb_h[j] = h;
        g_cb_l[j] = __float2bfloat16(x - __bfloat162float(h));
    }
}
__global__ void k_c2(const float* __restrict__ CB) {
    int k = blockIdx.x * blockDim.x + threadIdx.x;
    if (k < K_CODES) {
        const float* row = CB + (size_t)k * D_EMBV;
        float s = 0.f;
        #pragma unroll 8
        for (int e = 0; e < D_EMBV; e++) s += row[e] * row[e];
        g_c2[k] = s;
    }
}
__global__ void k_zero() { if (threadIdx.x < N_BATCH) g_loss[threadIdx.x] = 0.f; }

// ---------------- CBup = codebook @ W_up^T (small fp32 SIMT GEMM) ----------------
static __device__ __forceinline__ unsigned long long bcast2(float x) {
    unsigned long long r; asm("mov.b64 %0, {%1, %1};" : "=l"(r) : "f"(x)); return r;
}
static __device__ __forceinline__ void fma2(unsigned long long& c, unsigned long long a,
                                            unsigned long long b) {
    asm("fma.rn.f32x2 %0, %1, %2, %0;" : "+l"(c) : "l"(a), "l"(b));
}
static __device__ __forceinline__ float2 unpack2(unsigned long long v) {
    float2 f;
    f.x = __uint_as_float((unsigned)(v & 0xffffffffull));
    f.y = __uint_as_float((unsigned)(v >> 32));
    return f;
}
__global__ void k_cbup(const float* __restrict__ A, const float* __restrict__ W) {
    __shared__ __align__(16) float As[32][68];
    __shared__ __align__(16) float Bs[32][68];
    const int m0 = blockIdx.x * 64, n0 = blockIdx.y * 64;
    const int tid = threadIdx.x, tx = tid & 15, ty = tid >> 4;
    unsigned long long acc[4][2];
    #pragma unroll
    for (int i = 0; i < 4; i++) { acc[i][0] = 0ull; acc[i][1] = 0ull; }
    for (int kk = 0; kk < D_EMBV; kk += 32) {
        #pragma unroll
        for (int i = 0; i < 8; i++) {
            int idx = tid + i * 256, r = idx >> 5, c = idx & 31;
            As[c][r] = A[(size_t)(m0 + r) * D_EMBV + kk + c];
            Bs[c][r] = W[(size_t)(n0 + r) * D_EMBV + kk + c];
        }
        __syncthreads();
        #pragma unroll
        for (int k = 0; k < 32; k++) {
            float4 av = *(const float4*)&As[k][ty * 4];
            ulonglong2 bv = *(const ulonglong2*)&Bs[k][tx * 4];
            unsigned long long a0 = bcast2(av.x), a1 = bcast2(av.y);
            unsigned long long a2 = bcast2(av.z), a3 = bcast2(av.w);
            fma2(acc[0][0], a0, bv.x); fma2(acc[0][1], a0, bv.y);
            fma2(acc[1][0], a1, bv.x); fma2(acc[1][1], a1, bv.y);
            fma2(acc[2][0], a2, bv.x); fma2(acc[2][1], a2, bv.y);
            fma2(acc[3][0], a3, bv.x); fma2(acc[3][1], a3, bv.y);
        }
        __syncthreads();
    }
    #pragma unroll
    for (int i = 0; i < 4; i++) {
        float2 p0 = unpack2(acc[i][0]), p1 = unpack2(acc[i][1]);
        *(float4*)&g_cbup[(size_t)(m0 + ty * 4 + i) * D_INV + n0 + tx * 4] =
            make_float4(p0.x, p0.y, p1.x, p1.y);
    }
}

// ---------------- k_down: zed = z_e @ Wd^T (2-way split, 3-pass HMMA) ------------
// buffer (40960B): Ah@0 Al@10240 Bh@20480 Bl@30720; x2 buffers. rows 80B.
#define KD_BUF  40960
#define KD_SMEM 81920
__global__ void __launch_bounds__(256, 1) k_down(const float* __restrict__ A,
                                                 float* __restrict__ C) {
    extern __shared__ __align__(16) char sm[];
    const unsigned sb = smem_u32(sm);
    const int tid = threadIdx.x, lane = tid & 31, wid = tid >> 5;
    const int wr = wid >> 1, wc = wid & 1;
    const int m0 = blockIdx.x * 128, n0 = blockIdx.y * 128;

    float acc[2][8][4];
    #pragma unroll
    for (int mi = 0; mi < 2; mi++)
        #pragma unroll
        for (int ni = 0; ni < 8; ni++)
            #pragma unroll
            for (int q = 0; q < 4; q++) acc[mi][ni][q] = 0.f;

    float4 areg[4];
    uint4  bh[2], bl[2];

    #pragma unroll
    for (int i = 0; i < 4; i++) {
        int j = tid + i * 256, r = j >> 3, c4 = j & 7;
        areg[i] = *(const float4*)&A[(size_t)(m0 + r) * D_INV + c4 * 4];
    }
    #pragma unroll
    for (int i = 0; i < 2; i++) {
        int j = tid + i * 256, r = j >> 2, c = j & 3;
        size_t src = (size_t)(n0 + r) * D_INV + c * 8;
        bh[i] = *(const uint4*)&g_wd_h[src];
        bl[i] = *(const uint4*)&g_wd_l[src];
    }
    {
        char* base = sm;
        #pragma unroll
        for (int i = 0; i < 4; i++) {
            int j = tid + i * 256, r = j >> 3, c4 = j & 7;
            uint2 h, l; split2_f4(areg[i], h, l);
            unsigned off = r * 80 + c4 * 8;
            *(uint2*)(base + off) = h;
            *(uint2*)(base + 10240 + off) = l;
        }
        #pragma unroll
        for (int i = 0; i < 2; i++) {
            int j = tid + i * 256, r = j >> 2, c = j & 3;
            unsigned off = r * 80 + c * 16;
            *(uint4*)(base + 20480 + off) = bh[i];
            *(uint4*)(base + 30720 + off) = bl[i];
        }
    }
    __syncthreads();

    #pragma unroll 1
    for (int ch = 0; ch < 16; ch++) {
        int nxt = ch + 1;
        if (nxt < 16) {
            #pragma unroll
            for (int i = 0; i < 4; i++) {
                int j = tid + i * 256, r = j >> 3, c4 = j & 7;
                areg[i] = *(const float4*)&A[(size_t)(m0 + r) * D_INV + nxt * 32 + c4 * 4];
            }
            #pragma unroll
            for (int i = 0; i < 2; i++) {
                int j = tid + i * 256, r = j >> 2, c = j & 3;
                size_t src = (size_t)(n0 + r) * D_INV + nxt * 32 + c * 8;
                bh[i] = *(const uint4*)&g_wd_h[src];
                bl[i] = *(const uint4*)&g_wd_l[src];
            }
        }
        {
            unsigned bufb = sb + (ch & 1) * KD_BUF;
            #pragma unroll
            for (int s = 0; s < 2; s++) {
                unsigned a_h[2][4], a_l[2][4];
                #pragma unroll
                for (int mi = 0; mi < 2; mi++) {
                    unsigned off = (wr * 32 + mi * 16 + (lane & 15)) * 80 +
                                   ((lane >> 4) << 4) + s * 32;
                    LDSM4(a_h[mi], bufb + off);
                    LDSM4(a_l[mi], bufb + 10240 + off);
                }
                #pragma unroll
                for (int nh = 0; nh < 2; nh++) {
                    unsigned b_h[4][2], b_l[4][2];
                    #pragma unroll
                    for (int p = 0; p < 2; p++) {
                        int np = nh * 2 + p;
                        unsigned off = (wc * 64 + np * 16 + (lane & 7) +
                                        ((lane >> 4) << 3)) * 80 +
                                       (((lane >> 3) & 1) << 4) + s * 32;
                        LDSM4B(b_h[p * 2], b_h[p * 2 + 1], bufb + 20480 + off);
                        LDSM4B(b_l[p * 2], b_l[p * 2 + 1], bufb + 30720 + off);
                    }
                    #pragma unroll
                    for (int mi = 0; mi < 2; mi++)
                        #pragma unroll
                        for (int k = 0; k < 4; k++)
                            MMA_B16(acc[mi][nh * 4 + k], a_h[mi], b_h[k]);
                    #pragma unroll
                    for (int mi = 0; mi < 2; mi++)
                        #pragma unroll
                        for (int k = 0; k < 4; k++)
                            MMA_B16(acc[mi][nh * 4 + k], a_l[mi], b_h[k]);
                    #pragma unroll
                    for (int mi = 0; mi < 2; mi++)
                        #pragma unroll
                        for (int k = 0; k < 4; k++)
                            MMA_B16(acc[mi][nh * 4 + k], a_h[mi], b_l[k]);
                }
            }
        }
        if (nxt < 16) {
            char* base = sm + (nxt & 1) * KD_BUF;
            #pragma unroll
            for (int i = 0; i < 4; i++) {
                int j = tid + i * 256, r = j >> 3, c4 = j & 7;
                uint2 h, l; split2_f4(areg[i], h, l);
                unsigned off = r * 80 + c4 * 8;
                *(uint2*)(base + off) = h;
                *(uint2*)(base + 10240 + off) = l;
            }
            #pragma unroll
            for (int i = 0; i < 2; i++) {
                int j = tid + i * 256, r = j >> 2, c = j & 3;
                unsigned off = r * 80 + c * 16;
                *(uint4*)(base + 20480 + off) = bh[i];
                *(uint4*)(base + 30720 + off) = bl[i];
            }
        }
        __syncthreads();
    }
    #pragma unroll
    for (int mi = 0; mi < 2; mi++)
        #pragma unroll
        for (int h = 0; h < 2; h++) {
            int row = m0 + wr * 32 + mi * 16 + h * 8 + (lane >> 2);
            #pragma unroll
            for (int ni = 0; ni < 8; ni++) {
                int col = n0 + wc * 64 + ni * 8 + 2 * (lane & 3);
                *(float2*)&C[(size_t)row * D_EMBV + col] =
                    make_float2(acc[mi][ni][h * 2], acc[mi][ni][h * 2 + 1]);
            }
        }
}

// ---------------- k_dist: fused dist GEMM + top2 (3-pass, cp.async B staging) ----
// smem: Ah chunks 0..7 @0 (8*10240) | Al @81920 | B bufs @163840 (2 * 20480)
// reduction @204800: m1(1024B) i1(1024B) m2(1024B) -> total 207872
#define DS_AL   81920
#define DS_BB   163840
#define DS_RED  204800
#define DS_SMEM 207872
__global__ void __launch_bounds__(256, 1) k_dist(const float* __restrict__ Z,
                                                 float* __restrict__ code_f) {
    extern __shared__ __align__(16) char sm[];
    const unsigned sb = smem_u32(sm);
    const int tid = threadIdx.x, lane = tid & 31, wid = tid >> 5;
    const int wr = wid >> 1, wc = wid & 1;
    const int m0 = blockIdx.x * 128;

    // async B-tile loader: iteration it=(nt,ch) -> 128 codes x 32 dims, hi+lo
    auto load_b = [&](int it, int buf) {
        int nt = it >> 3, ch = it & 7;
        unsigned dbase = sb + DS_BB + buf * 20480;
        // 512 x 16B units per array; 2 units/thread each
        #pragma unroll
        for (int i = 0; i < 2; i++) {
            int u = tid + i * 256;
            int r = u >> 2, c = u & 3;
            unsigned doff = r * 80 + c * 16;
            size_t soff = (size_t)(nt * 128 + r) * D_EMBV + ch * 32 + c * 8;
            CP_ASYNC16(dbase + doff, (const void*)&g_cb_h[soff]);
            CP_ASYNC16(dbase + 10240 + doff, (const void*)&g_cb_l[soff]);
        }
        CP_COMMIT();
    };

    // kick off B tile 0 first so the copy overlaps the A-resident split below
    load_b(0, 0);

    // resident A: split zed[m0..+128, 0..256) into 8 chunk tiles (hi/lo)
    #pragma unroll 4
    for (int i = 0; i < 32; i++) {
        int j = tid + i * 256, r = j >> 6, col4 = j & 63;
        int ch = col4 >> 3, c4 = col4 & 7;
        float4 v = *(const float4*)&Z[(size_t)(m0 + r) * D_EMBV + col4 * 4];
        uint2 h, l; split2_f4(v, h, l);
        unsigned off = ch * 10240 + r * 80 + c4 * 8;
        *(uint2*)(sm + off) = h;
        *(uint2*)(sm + DS_AL + off) = l;
    }

    float acc[2][8][4];
    #pragma unroll
    for (int mi = 0; mi < 2; mi++)
        #pragma unroll
        for (int ni = 0; ni < 8; ni++)
            #pragma unroll
            for (int q = 0; q < 4; q++) acc[mi][ni][q] = 0.f;

    float t1[4], t2[4]; int ti[4];
    #pragma unroll
    for (int s = 0; s < 4; s++) { t1[s] = 3.4e38f; t2[s] = 3.4e38f; ti[s] = 0; }

    CP_WAIT0();
    __syncthreads();

    #pragma unroll 1
    for (int it = 0; it < 64; it++) {
        int nt = it >> 3, ch = it & 7;
        int nxt = it + 1;
        // issue async copy of next B tile into the other buffer
        if (nxt < 64) load_b(nxt, nxt & 1);
        // MMA: A chunk tile ch (resident) x B buffer it&1
        {
            unsigned abase = sb + ch * 10240;
            unsigned bbase = sb + DS_BB + (it & 1) * 20480;
            #pragma unroll
            for (int s = 0; s < 2; s++) {
                unsigned a_h[2][4], a_l[2][4];
                #pragma unroll
                for (int mi = 0; mi < 2; mi++) {
                    unsigned off = (wr * 32 + mi * 16 + (lane & 15)) * 80 +
                                   ((lane >> 4) << 4) + s * 32;
                    LDSM4(a_h[mi], abase + off);
                    LDSM4(a_l[mi], abase + DS_AL + off);
                }
                #pragma unroll
                for (int nh = 0; nh < 2; nh++) {
                    unsigned b_h[4][2], b_l[4][2];
                    #pragma unroll
                    for (int p = 0; p < 2; p++) {
                        int np = nh * 2 + p;
                        unsigned off = (wc * 64 + np * 16 + (lane & 7) +
                                        ((lane >> 4) << 3)) * 80 +
                                       (((lane >> 3) & 1) << 4) + s * 32;
                        LDSM4B(b_h[p * 2], b_h[p * 2 + 1], bbase + off);
                        LDSM4B(b_l[p * 2], b_l[p * 2 + 1], bbase + 10240 + off);
                    }
                    #pragma unroll
                    for (int mi = 0; mi < 2; mi++)
                        #pragma unroll
                        for (int k = 0; k < 4; k++)
                            MMA_B16(acc[mi][nh * 4 + k], a_h[mi], b_h[k]);
                    #pragma unroll
                    for (int mi = 0; mi < 2; mi++)
                        #pragma unroll
                        for (int k = 0; k < 4; k++)
                            MMA_B16(acc[mi][nh * 4 + k], a_l[mi], b_h[k]);
                    #pragma unroll
                    for (int mi = 0; mi < 2; mi++)
                        #pragma unroll
                        for (int k = 0; k < 4; k++)
                            MMA_B16(acc[mi][nh * 4 + k], a_h[mi], b_l[k]);
                }
            }
        }
        // end of N-tile: fold distances into running top-2
        if (ch == 7) {
            #pragma unroll
            for (int ni = 0; ni < 8; ni++)
                #pragma unroll
                for (int cc = 0; cc < 2; cc++) {
                    int g = nt * 128 + wc * 64 + ni * 8 + 2 * (lane & 3) + cc;
                    float c2v = __ldg(&g_c2[g]);
                    #pragma unroll
                    for (int mi = 0; mi < 2; mi++)
                        #pragma unroll
                        for (int h = 0; h < 2; h++) {
                            int slot = mi * 2 + h;
                            float d = c2v - 2.f * acc[mi][ni][h * 2 + cc];
                            if (d < t1[slot]) { t2[slot] = t1[slot]; t1[slot] = d; ti[slot] = g; }
                            else if (d < t2[slot]) { t2[slot] = d; }
                        }
                }
            #pragma unroll
            for (int mi = 0; mi < 2; mi++)
                #pragma unroll
                for (int ni = 0; ni < 8; ni++)
                    #pragma unroll
                    for (int q = 0; q < 4; q++) acc[mi][ni][q] = 0.f;
        }
        CP_WAIT0();
        __syncthreads();
    }

    // quad reduce (lanes sharing lane>>2 hold the same rows)
    #pragma unroll
    for (int s = 0; s < 4; s++) {
        #pragma unroll
        for (int off = 1; off <= 2; off <<= 1) {
            float o1 = __shfl_xor_sync(0xffffffffu, t1[s], off);
            float o2 = __shfl_xor_sync(0xffffffffu, t2[s], off);
            int oi = __shfl_xor_sync(0xffffffffu, ti[s], off);
            bool takeo = (o1 < t1[s]) || (o1 == t1[s] && oi < ti[s]);
            float nm2 = takeo ? fminf(t1[s], o2) : fminf(t2[s], o1);
            if (takeo) { t1[s] = o1; ti[s] = oi; }
            t2[s] = nm2;
        }
    }
    float* red_m1 = (float*)(sm + DS_RED);
    int*   red_i1 = (int*)(sm + DS_RED + 1024);
    float* red_m2 = (float*)(sm + DS_RED + 2048);
    if ((lane & 3) == 0) {
        #pragma unroll
        for (int mi = 0; mi < 2; mi++)
            #pragma unroll
            for (int h = 0; h < 2; h++) {
                int s = mi * 2 + h;
                int row = wr * 32 + mi * 16 + h * 8 + (lane >> 2);
                red_m1[row * 2 + wc] = t1[s];
                red_i1[row * 2 + wc] = ti[s];
                red_m2[row * 2 + wc] = t2[s];
            }
    }
    __syncthreads();
    if (tid < 128) {
        float m1a = red_m1[tid * 2], m2a = red_m2[tid * 2];
        int   i1a = red_i1[tid * 2];
        float m1b = red_m1[tid * 2 + 1], m2b = red_m2[tid * 2 + 1];
        int   i1b = red_i1[tid * 2 + 1];
        bool takeb = (m1b < m1a) || (m1b == m1a && i1b < i1a);
        float m1c = takeb ? m1b : m1a;
        int   i1c = takeb ? i1b : i1a;
        float m2c = takeb ? fminf(m1a, m2b) : fminf(m2a, m1b);
        int t = m0 + tid;
        g_code[t] = i1c;
        code_f[t] = (float)i1c;
        g_flag[t] = (m2c - m1c < 0.02f) ? 1 : 0;
    }
}

// ---------------- exact fp32 re-check for ambiguous tokens -----------------------
__global__ void k_fix(const float* __restrict__ Z, const float* __restrict__ CB,
                      float* __restrict__ code_f) {
    int t = blockIdx.x * 8 + (threadIdx.x >> 5);
    int lane = threadIdx.x & 31;
    if (!g_flag[t]) return;
    const float* z = Z + (size_t)t * D_EMBV;
    float best = 3.4e38f; int bi = K_CODES;
    for (int kk = lane * 32; kk < lane * 32 + 32; kk++) {
        const float* cr = CB + (size_t)kk * D_EMBV;
        float dot = 0.f;
        #pragma unroll 8
        for (int e = 0; e < D_EMBV; e++) dot += z[e] * cr[e];
        float d = g_c2[kk] - 2.f * dot;
        if (d < best) { best = d; bi = kk; }
    }
    #pragma unroll
    for (int o = 16; o > 0; o >>= 1) {
        float od = __shfl_xor_sync(0xffffffffu, best, o);
        int oi = __shfl_xor_sync(0xffffffffu, bi, o);
        if (od < best || (od == best && oi < bi)) { best = od; bi = oi; }
    }
    if (lane == 0) { g_code[t] = bi; code_f[t] = (float)bi; }
}

// ---------------- gather: zq[t] = CBup[code[t]] ----------------------------------
__global__ void k_gather(float* __restrict__ ZQ) {
    int idx = blockIdx.x * blockDim.x + threadIdx.x;
    int t = idx >> 7, j = idx & 127;
    int code = g_code[t];
    ((float4*)ZQ)[(size_t)t * 128 + j] = ((const float4*)g_cbup)[(size_t)code * 128 + j];
}

// ---------------- per-batch VQ losses --------------------------------------------
__global__ void k_loss(const float* __restrict__ Z, const float* __restrict__ CB) {
    int lane = threadIdx.x & 31;
    int t = (blockIdx.x * blockDim.x + threadIdx.x) >> 5;
    int code = g_code[t];
    float s = 0.f;
    #pragma unroll
    for (int i = 0; i < 8; i++) {
        int e = lane + 32 * i;
        float d = Z[(size_t)t * D_EMBV + e] - CB[(size_t)code * D_EMBV + e];
        s += d * d;
    }
    #pragma unroll
    for (int o = 16; o > 0; o >>= 1) s += __shfl_xor_sync(0xffffffffu, s, o);
    if (lane == 0) atomicAdd(&g_loss[t >> 12], s);
}
__global__ void k_finish(float* __restrict__ oc, float* __restrict__ ob) {
    int i = threadIdx.x;
    if (i < N_BATCH) {
        float v = g_loss[i] * (1.0f / ((float)T_SEQ * (float)D_EMBV));
        oc[i] = v; ob[i] = v;
    }
}

// ---------------- launcher --------------------------------------------------------
extern "C" void kernel_launch(void* const* d_in, const int* in_sizes, int n_in,
                              void* d_out, int out_size) {
    const float* z_e    = (const float*)d_in[0];
    const float* cb     = (const float*)d_in[1];
    const float* w_down = (const float*)d_in[2];
    const float* w_up   = (const float*)d_in[3];

    float* out     = (float*)d_out;
    float* zq      = out;
    float* zed     = out + (size_t)BT_TOK * D_INV;
    float* codef   = out + (size_t)BT_TOK * (D_INV + D_EMBV);
    float* lcommit = codef + BT_TOK;
    float* lcb     = lcommit + N_BATCH;

    cudaFuncSetAttribute(k_down, cudaFuncAttributeMaxDynamicSharedMemorySize, KD_SMEM);
    cudaFuncSetAttribute(k_dist, cudaFuncAttributeMaxDynamicSharedMemorySize, DS_SMEM);

    // NOTE: k_cbup moved AFTER k_down so the positional ncu capture profiles k_down.
    k_prep<<<(D_EMBV * D_INV + K_CODES * D_EMBV + 255) / 256, 256>>>(w_down, cb);
    k_c2<<<(K_CODES + 255) / 256, 256>>>(cb);
    k_zero<<<1, 32>>>();
    k_down<<<dim3(BT_TOK / 128, 2), 256, KD_SMEM>>>(z_e, zed);
    k_cbup<<<dim3(K_CODES / 64, D_INV / 64), 256>>>(cb, w_up);
    k_dist<<<BT_TOK / 128, 256, DS_SMEM>>>(zed, codef);
    k_fix<<<BT_TOK / 8, 256>>>(zed, cb, codef);
    k_gather<<<(BT_TOK * 128) / 256, 256>>>(zq);
    k_loss<<<BT_TOK / 8, 256>>>(zed, cb);
    k_finish<<<1, 32>>>(lcommit, lcb);
}

// round 15
// speedup vs baseline: 1.4261x; 1.0286x over previous
#include <cuda_runtime.h>
#include <cuda_bf16.h>

#define BT_TOK  65536
#define D_INV   512
#define D_EMBV  256
#define K_CODES 1024
#define N_BATCH 16
#define T_SEQ   4096

// ---------------- device scratch ---------------------------------------------
__device__ int           g_code[BT_TOK];
__device__ int           g_flag[BT_TOK];
__device__ float         g_c2[K_CODES];
__device__ float         g_loss[N_BATCH];
__device__ __nv_bfloat16 g_wd_h[D_EMBV * D_INV];
__device__ __nv_bfloat16 g_wd_l[D_EMBV * D_INV];
__device__ __nv_bfloat16 g_cb_h[K_CODES * D_EMBV];
__device__ __nv_bfloat16 g_cb_l[K_CODES * D_EMBV];
__device__ float         g_cbup[K_CODES * D_INV];

// ---------------- helpers -------------------------------------------------------
static __device__ __forceinline__ unsigned smem_u32(const void* p) {
    unsigned a;
    asm("{ .reg .u64 t; cvta.to.shared.u64 t, %1; cvt.u32.u64 %0, t; }"
        : "=r"(a) : "l"(p));
    return a;
}

#define LDSM4(d, addr) \
    asm volatile("ldmatrix.sync.aligned.m8n8.x4.shared.b16 {%0,%1,%2,%3}, [%4];" \
        : "=r"((d)[0]), "=r"((d)[1]), "=r"((d)[2]), "=r"((d)[3]) : "r"(addr))

#define LDSM4B(b0, b1, addr) \
    asm volatile("ldmatrix.sync.aligned.m8n8.x4.shared.b16 {%0,%1,%2,%3}, [%4];" \
        : "=r"((b0)[0]), "=r"((b0)[1]), "=r"((b1)[0]), "=r"((b1)[1]) : "r"(addr))

#define MMA_B16(c, a, b) \
    asm volatile("mma.sync.aligned.m16n8k16.row.col.f32.bf16.bf16.f32 " \
        "{%0,%1,%2,%3},{%4,%5,%6,%7},{%8,%9},{%0,%1,%2,%3};" \
        : "+f"((c)[0]), "+f"((c)[1]), "+f"((c)[2]), "+f"((c)[3]) \
        : "r"((a)[0]), "r"((a)[1]), "r"((a)[2]), "r"((a)[3]), "r"((b)[0]), "r"((b)[1]))

static __device__ __forceinline__ unsigned pack_bf2(float x, float y) {
    __nv_bfloat162 t = __float22bfloat162_rn(make_float2(x, y));
    return *(unsigned*)&t;
}

// 2-way split: v -> hi, lo  (each uint2 = 4 bf16)
static __device__ __forceinline__ void split2_f4(float4 v, uint2& h, uint2& l) {
    __nv_bfloat162 h01 = __float22bfloat162_rn(make_float2(v.x, v.y));
    __nv_bfloat162 h23 = __float22bfloat162_rn(make_float2(v.z, v.w));
    float r0 = v.x - __bfloat162float(h01.x);
    float r1 = v.y - __bfloat162float(h01.y);
    float r2 = v.z - __bfloat162float(h23.x);
    float r3 = v.w - __bfloat162float(h23.y);
    h.x = *(unsigned*)&h01; h.y = *(unsigned*)&h23;
    l.x = pack_bf2(r0, r1); l.y = pack_bf2(r2, r3);
}

// ---------------- prep kernels ---------------------------------------------------
__global__ void k_prep(const float* __restrict__ wd, const float* __restrict__ cb) {
    int i = blockIdx.x * blockDim.x + threadIdx.x;
    if (i < D_EMBV * D_INV) {
        float x = wd[i];
        __nv_bfloat16 h = __float2bfloat16(x);
        g_wd_h[i] = h;
        g_wd_l[i] = __float2bfloat16(x - __bfloat162float(h));
    }
    int j = i - D_EMBV * D_INV;
    if (j >= 0 && j < K_CODES * D_EMBV) {
        float x = cb[j];
        __nv_bfloat16 h = __float2bfloat16(x);
        g_cb_h[j] = h;
        g_cb_l[j] = __float2bfloat16(x - __bfloat162float(h));
    }
}
__global__ void k_c2(const float* __restrict__ CB) {
    int k = blockIdx.x * blockDim.x + threadIdx.x;
    if (k < K_CODES) {
        const float* row = CB + (size_t)k * D_EMBV;
        float s = 0.f;
        #pragma unroll 8
        for (int e = 0; e < D_EMBV; e++) s += row[e] * row[e];
        g_c2[k] = s;
    }
}
__global__ void k_zero() { if (threadIdx.x < N_BATCH) g_loss[threadIdx.x] = 0.f; }

// ---------------- CBup = codebook @ W_up^T (small fp32 SIMT GEMM) ----------------
static __device__ __forceinline__ unsigned long long bcast2(float x) {
    unsigned long long r; asm("mov.b64 %0, {%1, %1};" : "=l"(r) : "f"(x)); return r;
}
static __device__ __forceinline__ void fma2(unsigned long long& c, unsigned long long a,
                                            unsigned long long b) {
    asm("fma.rn.f32x2 %0, %1, %2, %0;" : "+l"(c) : "l"(a), "l"(b));
}
static __device__ __forceinline__ float2 unpack2(unsigned long long v) {
    float2 f;
    f.x = __uint_as_float((unsigned)(v & 0xffffffffull));
    f.y = __uint_as_float((unsigned)(v >> 32));
    return f;
}
__global__ void k_cbup(const float* __restrict__ A, const float* __restrict__ W) {
    __shared__ __align__(16) float As[32][68];
    __shared__ __align__(16) float Bs[32][68];
    const int m0 = blockIdx.x * 64, n0 = blockIdx.y * 64;
    const int tid = threadIdx.x, tx = tid & 15, ty = tid >> 4;
    unsigned long long acc[4][2];
    #pragma unroll
    for (int i = 0; i < 4; i++) { acc[i][0] = 0ull; acc[i][1] = 0ull; }
    for (int kk = 0; kk < D_EMBV; kk += 32) {
        #pragma unroll
        for (int i = 0; i < 8; i++) {
            int idx = tid + i * 256, r = idx >> 5, c = idx & 31;
            As[c][r] = A[(size_t)(m0 + r) * D_EMBV + kk + c];
            Bs[c][r] = W[(size_t)(n0 + r) * D_EMBV + kk + c];
        }
        __syncthreads();
        #pragma unroll
        for (int k = 0; k < 32; k++) {
            float4 av = *(const float4*)&As[k][ty * 4];
            ulonglong2 bv = *(const ulonglong2*)&Bs[k][tx * 4];
            unsigned long long a0 = bcast2(av.x), a1 = bcast2(av.y);
            unsigned long long a2 = bcast2(av.z), a3 = bcast2(av.w);
            fma2(acc[0][0], a0, bv.x); fma2(acc[0][1], a0, bv.y);
            fma2(acc[1][0], a1, bv.x); fma2(acc[1][1], a1, bv.y);
            fma2(acc[2][0], a2, bv.x); fma2(acc[2][1], a2, bv.y);
            fma2(acc[3][0], a3, bv.x); fma2(acc[3][1], a3, bv.y);
        }
        __syncthreads();
    }
    #pragma unroll
    for (int i = 0; i < 4; i++) {
        float2 p0 = unpack2(acc[i][0]), p1 = unpack2(acc[i][1]);
        *(float4*)&g_cbup[(size_t)(m0 + ty * 4 + i) * D_INV + n0 + tx * 4] =
            make_float4(p0.x, p0.y, p1.x, p1.y);
    }
}

// ---------------- k_down: zed = z_e @ Wd^T (2-way split, 3-pass HMMA) ------------
// buffer (40960B): Ah@0 Al@10240 Bh@20480 Bl@30720; x2 buffers. rows 80B.
#define KD_BUF  40960
#define KD_SMEM 81920
__global__ void __launch_bounds__(256, 1) k_down(const float* __restrict__ A,
                                                 float* __restrict__ C) {
    extern __shared__ __align__(16) char sm[];
    const unsigned sb = smem_u32(sm);
    const int tid = threadIdx.x, lane = tid & 31, wid = tid >> 5;
    const int wr = wid >> 1, wc = wid & 1;
    const int m0 = blockIdx.x * 128, n0 = blockIdx.y * 128;

    float acc[2][8][4];
    #pragma unroll
    for (int mi = 0; mi < 2; mi++)
        #pragma unroll
        for (int ni = 0; ni < 8; ni++)
            #pragma unroll
            for (int q = 0; q < 4; q++) acc[mi][ni][q] = 0.f;

    float4 areg[4];
    uint4  bh[2], bl[2];

    #pragma unroll
    for (int i = 0; i < 4; i++) {
        int j = tid + i * 256, r = j >> 3, c4 = j & 7;
        areg[i] = *(const float4*)&A[(size_t)(m0 + r) * D_INV + c4 * 4];
    }
    #pragma unroll
    for (int i = 0; i < 2; i++) {
        int j = tid + i * 256, r = j >> 2, c = j & 3;
        size_t src = (size_t)(n0 + r) * D_INV + c * 8;
        bh[i] = *(const uint4*)&g_wd_h[src];
        bl[i] = *(const uint4*)&g_wd_l[src];
    }
    {
        char* base = sm;
        #pragma unroll
        for (int i = 0; i < 4; i++) {
            int j = tid + i * 256, r = j >> 3, c4 = j & 7;
            uint2 h, l; split2_f4(areg[i], h, l);
            unsigned off = r * 80 + c4 * 8;
            *(uint2*)(base + off) = h;
            *(uint2*)(base + 10240 + off) = l;
        }
        #pragma unroll
        for (int i = 0; i < 2; i++) {
            int j = tid + i * 256, r = j >> 2, c = j & 3;
            unsigned off = r * 80 + c * 16;
            *(uint4*)(base + 20480 + off) = bh[i];
            *(uint4*)(base + 30720 + off) = bl[i];
        }
    }
    __syncthreads();

    #pragma unroll 1
    for (int ch = 0; ch < 16; ch++) {
        int nxt = ch + 1;
        if (nxt < 16) {
            #pragma unroll
            for (int i = 0; i < 4; i++) {
                int j = tid + i * 256, r = j >> 3, c4 = j & 7;
                areg[i] = *(const float4*)&A[(size_t)(m0 + r) * D_INV + nxt * 32 + c4 * 4];
            }
            #pragma unroll
            for (int i = 0; i < 2; i++) {
                int j = tid + i * 256, r = j >> 2, c = j & 3;
                size_t src = (size_t)(n0 + r) * D_INV + nxt * 32 + c * 8;
                bh[i] = *(const uint4*)&g_wd_h[src];
                bl[i] = *(const uint4*)&g_wd_l[src];
            }
        }
        {
            unsigned bufb = sb + (ch & 1) * KD_BUF;
            #pragma unroll
            for (int s = 0; s < 2; s++) {
                unsigned a_h[2][4], a_l[2][4];
                #pragma unroll
                for (int mi = 0; mi < 2; mi++) {
                    unsigned off = (wr * 32 + mi * 16 + (lane & 15)) * 80 +
                                   ((lane >> 4) << 4) + s * 32;
                    LDSM4(a_h[mi], bufb + off);
                    LDSM4(a_l[mi], bufb + 10240 + off);
                }
                #pragma unroll
                for (int nh = 0; nh < 2; nh++) {
                    unsigned b_h[4][2], b_l[4][2];
                    #pragma unroll
                    for (int p = 0; p < 2; p++) {
                        int np = nh * 2 + p;
                        unsigned off = (wc * 64 + np * 16 + (lane & 7) +
                                        ((lane >> 4) << 3)) * 80 +
                                       (((lane >> 3) & 1) << 4) + s * 32;
                        LDSM4B(b_h[p * 2], b_h[p * 2 + 1], bufb + 20480 + off);
                        LDSM4B(b_l[p * 2], b_l[p * 2 + 1], bufb + 30720 + off);
                    }
                    #pragma unroll
                    for (int mi = 0; mi < 2; mi++)
                        #pragma unroll
                        for (int k = 0; k < 4; k++)
                            MMA_B16(acc[mi][nh * 4 + k], a_h[mi], b_h[k]);
                    #pragma unroll
                    for (int mi = 0; mi < 2; mi++)
                        #pragma unroll
                        for (int k = 0; k < 4; k++)
                            MMA_B16(acc[mi][nh * 4 + k], a_l[mi], b_h[k]);
                    #pragma unroll
                    for (int mi = 0; mi < 2; mi++)
                        #pragma unroll
                        for (int k = 0; k < 4; k++)
                            MMA_B16(acc[mi][nh * 4 + k], a_h[mi], b_l[k]);
                }
            }
        }
        if (nxt < 16) {
            char* base = sm + (nxt & 1) * KD_BUF;
            #pragma unroll
            for (int i = 0; i < 4; i++) {
                int j = tid + i * 256, r = j >> 3, c4 = j & 7;
                uint2 h, l; split2_f4(areg[i], h, l);
                unsigned off = r * 80 + c4 * 8;
                *(uint2*)(base + off) = h;
                *(uint2*)(base + 10240 + off) = l;
            }
            #pragma unroll
            for (int i = 0; i < 2; i++) {
                int j = tid + i * 256, r = j >> 2, c = j & 3;
                unsigned off = r * 80 + c * 16;
                *(uint4*)(base + 20480 + off) = bh[i];
                *(uint4*)(base + 30720 + off) = bl[i];
            }
        }
        __syncthreads();
    }
    #pragma unroll
    for (int mi = 0; mi < 2; mi++)
        #pragma unroll
        for (int h = 0; h < 2; h++) {
            int row = m0 + wr * 32 + mi * 16 + h * 8 + (lane >> 2);
            #pragma unroll
            for (int ni = 0; ni < 8; ni++) {
                int col = n0 + wc * 64 + ni * 8 + 2 * (lane & 3);
                *(float2*)&C[(size_t)row * D_EMBV + col] =
                    make_float2(acc[mi][ni][h * 2], acc[mi][ni][h * 2 + 1]);
            }
        }
}

// ---------------- k_dist: fused dist GEMM + top2 argmin (bf16 2-split, 3-pass) ---
// smem: Ah chunks 0..7 @0 (8*10240) | Al @81920 | B bufs @163840 (2 * 20480)
// reduction @204800: m1(1024B) i1(1024B) m2(1024B) -> total 207872
#define DS_AL   81920
#define DS_BB   163840
#define DS_RED  204800
#define DS_SMEM 207872
__global__ void __launch_bounds__(256, 1) k_dist(const float* __restrict__ Z,
                                                 float* __restrict__ code_f) {
    extern __shared__ __align__(16) char sm[];
    const unsigned sb = smem_u32(sm);
    const int tid = threadIdx.x, lane = tid & 31, wid = tid >> 5;
    const int wr = wid >> 1, wc = wid & 1;
    const int m0 = blockIdx.x * 128;

    // resident A: split zed[m0..+128, 0..256) into 8 chunk tiles (hi/lo)
    #pragma unroll 4
    for (int i = 0; i < 32; i++) {
        int j = tid + i * 256, r = j >> 6, col4 = j & 63;
        int ch = col4 >> 3, c4 = col4 & 7;
        float4 v = *(const float4*)&Z[(size_t)(m0 + r) * D_EMBV + col4 * 4];
        uint2 h, l; split2_f4(v, h, l);
        unsigned off = ch * 10240 + r * 80 + c4 * 8;
        *(uint2*)(sm + off) = h;
        *(uint2*)(sm + DS_AL + off) = l;
    }

    float acc[2][8][4];
    #pragma unroll
    for (int mi = 0; mi < 2; mi++)
        #pragma unroll
        for (int ni = 0; ni < 8; ni++)
            #pragma unroll
            for (int q = 0; q < 4; q++) acc[mi][ni][q] = 0.f;

    float t1[4], t2[4]; int ti[4];
    #pragma unroll
    for (int s = 0; s < 4; s++) { t1[s] = 3.4e38f; t2[s] = 3.4e38f; ti[s] = 0; }

    uint4 pbh[2], pbl[2];
    #pragma unroll
    for (int i = 0; i < 2; i++) {
        int j = tid + i * 256, r = j >> 2, c = j & 3;
        size_t src = (size_t)r * D_EMBV + c * 8;
        pbh[i] = *(const uint4*)&g_cb_h[src];
        pbl[i] = *(const uint4*)&g_cb_l[src];
    }
    {
        char* base = sm + DS_BB;
        #pragma unroll
        for (int i = 0; i < 2; i++) {
            int j = tid + i * 256, r = j >> 2, c = j & 3;
            unsigned off = r * 80 + c * 16;
            *(uint4*)(base + off) = pbh[i];
            *(uint4*)(base + 10240 + off) = pbl[i];
        }
    }
    __syncthreads();

    #pragma unroll 1
    for (int it = 0; it < 64; it++) {
        int nt = it >> 3, ch = it & 7;
        int nxt = it + 1;
        if (nxt < 64) {
            int nnt = nxt >> 3, nch = nxt & 7;
            #pragma unroll
            for (int i = 0; i < 2; i++) {
                int j = tid + i * 256, r = j >> 2, c = j & 3;
                size_t src = (size_t)(nnt * 128 + r) * D_EMBV + nch * 32 + c * 8;
                pbh[i] = *(const uint4*)&g_cb_h[src];
                pbl[i] = *(const uint4*)&g_cb_l[src];
            }
        }
        {
            unsigned abase = sb + ch * 10240;
            unsigned bbase = sb + DS_BB + (it & 1) * 20480;
            #pragma unroll
            for (int s = 0; s < 2; s++) {
                unsigned a_h[2][4], a_l[2][4];
                #pragma unroll
                for (int mi = 0; mi < 2; mi++) {
                    unsigned off = (wr * 32 + mi * 16 + (lane & 15)) * 80 +
                                   ((lane >> 4) << 4) + s * 32;
                    LDSM4(a_h[mi], abase + off);
                    LDSM4(a_l[mi], abase + DS_AL + off);
                }
                #pragma unroll
                for (int nh = 0; nh < 2; nh++) {
                    unsigned b_h[4][2], b_l[4][2];
                    #pragma unroll
                    for (int p = 0; p < 2; p++) {
                        int np = nh * 2 + p;
                        unsigned off = (wc * 64 + np * 16 + (lane & 7) +
                                        ((lane >> 4) << 3)) * 80 +
                                       (((lane >> 3) & 1) << 4) + s * 32;
                        LDSM4B(b_h[p * 2], b_h[p * 2 + 1], bbase + off);
                        LDSM4B(b_l[p * 2], b_l[p * 2 + 1], bbase + 10240 + off);
                    }
                    #pragma unroll
                    for (int mi = 0; mi < 2; mi++)
                        #pragma unroll
                        for (int k = 0; k < 4; k++)
                            MMA_B16(acc[mi][nh * 4 + k], a_h[mi], b_h[k]);
                    #pragma unroll
                    for (int mi = 0; mi < 2; mi++)
                        #pragma unroll
                        for (int k = 0; k < 4; k++)
                            MMA_B16(acc[mi][nh * 4 + k], a_l[mi], b_h[k]);
                    #pragma unroll
                    for (int mi = 0; mi < 2; mi++)
                        #pragma unroll
                        for (int k = 0; k < 4; k++)
                            MMA_B16(acc[mi][nh * 4 + k], a_h[mi], b_l[k]);
                }
            }
        }
        if (ch == 7) {
            #pragma unroll
            for (int ni = 0; ni < 8; ni++)
                #pragma unroll
                for (int cc = 0; cc < 2; cc++) {
                    int g = nt * 128 + wc * 64 + ni * 8 + 2 * (lane & 3) + cc;
                    float c2v = __ldg(&g_c2[g]);
                    #pragma unroll
                    for (int mi = 0; mi < 2; mi++)
                        #pragma unroll
                        for (int h = 0; h < 2; h++) {
                            int slot = mi * 2 + h;
                            float d = c2v - 2.f * acc[mi][ni][h * 2 + cc];
                            if (d < t1[slot]) { t2[slot] = t1[slot]; t1[slot] = d; ti[slot] = g; }
                            else if (d < t2[slot]) { t2[slot] = d; }
                        }
                }
            #pragma unroll
            for (int mi = 0; mi < 2; mi++)
                #pragma unroll
                for (int ni = 0; ni < 8; ni++)
                    #pragma unroll
                    for (int q = 0; q < 4; q++) acc[mi][ni][q] = 0.f;
        }
        if (nxt < 64) {
            char* base = sm + DS_BB + (nxt & 1) * 20480;
            #pragma unroll
            for (int i = 0; i < 2; i++) {
                int j = tid + i * 256, r = j >> 2, c = j & 3;
                unsigned off = r * 80 + c * 16;
                *(uint4*)(base + off) = pbh[i];
                *(uint4*)(base + 10240 + off) = pbl[i];
            }
        }
        __syncthreads();
    }

    // quad reduce (lanes sharing lane>>2 hold the same rows)
    #pragma unroll
    for (int s = 0; s < 4; s++) {
        #pragma unroll
        for (int off = 1; off <= 2; off <<= 1) {
            float o1 = __shfl_xor_sync(0xffffffffu, t1[s], off);
            float o2 = __shfl_xor_sync(0xffffffffu, t2[s], off);
            int oi = __shfl_xor_sync(0xffffffffu, ti[s], off);
            bool takeo = (o1 < t1[s]) || (o1 == t1[s] && oi < ti[s]);
            float nm2 = takeo ? fminf(t1[s], o2) : fminf(t2[s], o1);
            if (takeo) { t1[s] = o1; ti[s] = oi; }
            t2[s] = nm2;
        }
    }
    float* red_m1 = (float*)(sm + DS_RED);
    int*   red_i1 = (int*)(sm + DS_RED + 1024);
    float* red_m2 = (float*)(sm + DS_RED + 2048);
    if ((lane & 3) == 0) {
        #pragma unroll
        for (int mi = 0; mi < 2; mi++)
            #pragma unroll
            for (int h = 0; h < 2; h++) {
                int s = mi * 2 + h;
                int row = wr * 32 + mi * 16 + h * 8 + (lane >> 2);
                red_m1[row * 2 + wc] = t1[s];
                red_i1[row * 2 + wc] = ti[s];
                red_m2[row * 2 + wc] = t2[s];
            }
    }
    __syncthreads();
    if (tid < 128) {
        float m1a = red_m1[tid * 2], m2a = red_m2[tid * 2];
        int   i1a = red_i1[tid * 2];
        float m1b = red_m1[tid * 2 + 1], m2b = red_m2[tid * 2 + 1];
        int   i1b = red_i1[tid * 2 + 1];
        bool takeb = (m1b < m1a) || (m1b == m1a && i1b < i1a);
        float m1c = takeb ? m1b : m1a;
        int   i1c = takeb ? i1b : i1a;
        float m2c = takeb ? fminf(m1a, m2b) : fminf(m2a, m1b);
        int t = m0 + tid;
        g_code[t] = i1c;
        code_f[t] = (float)i1c;
        g_flag[t] = (m2c - m1c < 0.02f) ? 1 : 0;
    }
}

// ---------------- exact fp32 re-check for ambiguous tokens -----------------------
__global__ void k_fix(const float* __restrict__ Z, const float* __restrict__ CB,
                      float* __restrict__ code_f) {
    int t = blockIdx.x * 8 + (threadIdx.x >> 5);
    int lane = threadIdx.x & 31;
    if (!g_flag[t]) return;
    const float* z = Z + (size_t)t * D_EMBV;
    float best = 3.4e38f; int bi = K_CODES;
    for (int kk = lane * 32; kk < lane * 32 + 32; kk++) {
        const float* cr = CB + (size_t)kk * D_EMBV;
        float dot = 0.f;
        #pragma unroll 8
        for (int e = 0; e < D_EMBV; e++) dot += z[e] * cr[e];
        float d = g_c2[kk] - 2.f * dot;
        if (d < best) { best = d; bi = kk; }
    }
    #pragma unroll
    for (int o = 16; o > 0; o >>= 1) {
        float od = __shfl_xor_sync(0xffffffffu, best, o);
        int oi = __shfl_xor_sync(0xffffffffu, bi, o);
        if (od < best || (od == best && oi < bi)) { best = od; bi = oi; }
    }
    if (lane == 0) { g_code[t] = bi; code_f[t] = (float)bi; }
}

// ---------------- gather: zq[t] = CBup[code[t]] ----------------------------------
__global__ void k_gather(float* __restrict__ ZQ) {
    int idx = blockIdx.x * blockDim.x + threadIdx.x;
    int t = idx >> 7, j = idx & 127;
    int code = g_code[t];
    ((float4*)ZQ)[(size_t)t * 128 + j] = ((const float4*)g_cbup)[(size_t)code * 128 + j];
}

// ---------------- per-batch VQ losses --------------------------------------------
__global__ void k_loss(const float* __restrict__ Z, const float* __restrict__ CB) {
    int lane = threadIdx.x & 31;
    int t = (blockIdx.x * blockDim.x + threadIdx.x) >> 5;
    int code = g_code[t];
    float s = 0.f;
    #pragma unroll
    for (int i = 0; i < 8; i++) {
        int e = lane + 32 * i;
        float d = Z[(size_t)t * D_EMBV + e] - CB[(size_t)code * D_EMBV + e];
        s += d * d;
    }
    #pragma unroll
    for (int o = 16; o > 0; o >>= 1) s += __shfl_xor_sync(0xffffffffu, s, o);
    if (lane == 0) atomicAdd(&g_loss[t >> 12], s);
}
__global__ void k_finish(float* __restrict__ oc, float* __restrict__ ob) {
    int i = threadIdx.x;
    if (i < N_BATCH) {
        float v = g_loss[i] * (1.0f / ((float)T_SEQ * (float)D_EMBV));
        oc[i] = v; ob[i] = v;
    }
}

// ---------------- launcher --------------------------------------------------------
extern "C" void kernel_launch(void* const* d_in, const int* in_sizes, int n_in,
                              void* d_out, int out_size) {
    const float* z_e    = (const float*)d_in[0];
    const float* cb     = (const float*)d_in[1];
    const float* w_down = (const float*)d_in[2];
    const float* w_up   = (const float*)d_in[3];

    float* out     = (float*)d_out;
    float* zq      = out;
    float* zed     = out + (size_t)BT_TOK * D_INV;
    float* codef   = out + (size_t)BT_TOK * (D_INV + D_EMBV);
    float* lcommit = codef + BT_TOK;
    float* lcb     = lcommit + N_BATCH;

    cudaFuncSetAttribute(k_down, cudaFuncAttributeMaxDynamicSharedMemorySize, KD_SMEM);
    cudaFuncSetAttribute(k_dist, cudaFuncAttributeMaxDynamicSharedMemorySize, DS_SMEM);

    // k_dist placed 4th so the positional ncu capture profiles it this round.
    k_prep<<<(D_EMBV * D_INV + K_CODES * D_EMBV + 255) / 256, 256>>>(w_down, cb);
    k_c2<<<(K_CODES + 255) / 256, 256>>>(cb);
    k_down<<<dim3(BT_TOK / 128, 2), 256, KD_SMEM>>>(z_e, zed);
    k_dist<<<BT_TOK / 128, 256, DS_SMEM>>>(zed, codef);
    k_cbup<<<dim3(K_CODES / 64, D_INV / 64), 256>>>(cb, w_up);
    k_zero<<<1, 32>>>();
    k_fix<<<BT_TOK / 8, 256>>>(zed, cb, codef);
    k_gather<<<(BT_TOK * 128) / 256, 256>>>(zq);
    k_loss<<<BT_TOK / 8, 256>>>(zed, cb);
    k_finish<<<1, 32>>>(lcommit, lcb);
}

// round 16
// speedup vs baseline: 1.9222x; 1.3479x over previous
#include <cuda_runtime.h>
#include <cuda_bf16.h>

#define BT_TOK  65536
#define D_INV   512
#define D_EMBV  256
#define K_CODES 1024
#define N_BATCH 16
#define T_SEQ   4096

// ---------------- device scratch ---------------------------------------------
__device__ int           g_code[BT_TOK];
__device__ int           g_cnt_f;
__device__ int           g_list_f[BT_TOK];
__device__ float         g_c2[K_CODES];
__device__ float         g_loss[N_BATCH];
__device__ __nv_bfloat16 g_wd_h[D_EMBV * D_INV];
__device__ __nv_bfloat16 g_wd_l[D_EMBV * D_INV];
__device__ __nv_bfloat16 g_cb_h[K_CODES * D_EMBV];
__device__ __nv_bfloat16 g_cb_l[K_CODES * D_EMBV];
__device__ float         g_cbup[K_CODES * D_INV];

// ---------------- helpers -------------------------------------------------------
static __device__ __forceinline__ unsigned smem_u32(const void* p) {
    unsigned a;
    asm("{ .reg .u64 t; cvta.to.shared.u64 t, %1; cvt.u32.u64 %0, t; }"
        : "=r"(a) : "l"(p));
    return a;
}

#define LDSM4(d, addr) \
    asm volatile("ldmatrix.sync.aligned.m8n8.x4.shared.b16 {%0,%1,%2,%3}, [%4];" \
        : "=r"((d)[0]), "=r"((d)[1]), "=r"((d)[2]), "=r"((d)[3]) : "r"(addr))

#define LDSM4B(b0, b1, addr) \
    asm volatile("ldmatrix.sync.aligned.m8n8.x4.shared.b16 {%0,%1,%2,%3}, [%4];" \
        : "=r"((b0)[0]), "=r"((b0)[1]), "=r"((b1)[0]), "=r"((b1)[1]) : "r"(addr))

#define MMA_B16(c, a, b) \
    asm volatile("mma.sync.aligned.m16n8k16.row.col.f32.bf16.bf16.f32 " \
        "{%0,%1,%2,%3},{%4,%5,%6,%7},{%8,%9},{%0,%1,%2,%3};" \
        : "+f"((c)[0]), "+f"((c)[1]), "+f"((c)[2]), "+f"((c)[3]) \
        : "r"((a)[0]), "r"((a)[1]), "r"((a)[2]), "r"((a)[3]), "r"((b)[0]), "r"((b)[1]))

static __device__ __forceinline__ unsigned pack_bf2(float x, float y) {
    __nv_bfloat162 t = __float22bfloat162_rn(make_float2(x, y));
    return *(unsigned*)&t;
}

// 2-way split: v -> hi, lo  (each uint2 = 4 bf16)
static __device__ __forceinline__ void split2_f4(float4 v, uint2& h, uint2& l) {
    __nv_bfloat162 h01 = __float22bfloat162_rn(make_float2(v.x, v.y));
    __nv_bfloat162 h23 = __float22bfloat162_rn(make_float2(v.z, v.w));
    float r0 = v.x - __bfloat162float(h01.x);
    float r1 = v.y - __bfloat162float(h01.y);
    float r2 = v.z - __bfloat162float(h23.x);
    float r3 = v.w - __bfloat162float(h23.y);
    h.x = *(unsigned*)&h01; h.y = *(unsigned*)&h23;
    l.x = pack_bf2(r0, r1); l.y = pack_bf2(r2, r3);
}

// ---------------- prep kernels ---------------------------------------------------
__global__ void k_prep(const float* __restrict__ wd, const float* __restrict__ cb) {
    int i = blockIdx.x * blockDim.x + threadIdx.x;
    if (i < D_EMBV * D_INV) {
        float x = wd[i];
        __nv_bfloat16 h = __float2bfloat16(x);
        g_wd_h[i] = h;
        g_wd_l[i] = __float2bfloat16(x - __bfloat162float(h));
    }
    int j = i - D_EMBV * D_INV;
    if (j >= 0 && j < K_CODES * D_EMBV) {
        float x = cb[j];
        __nv_bfloat16 h = __float2bfloat16(x);
        g_cb_h[j] = h;
        g_cb_l[j] = __float2bfloat16(x - __bfloat162float(h));
    }
}
__global__ void k_c2(const float* __restrict__ CB) {
    int k = blockIdx.x * blockDim.x + threadIdx.x;
    if (k == 0) g_cnt_f = 0;
    if (k < K_CODES) {
        const float* row = CB + (size_t)k * D_EMBV;
        float s = 0.f;
        #pragma unroll 8
        for (int e = 0; e < D_EMBV; e++) s += row[e] * row[e];
        g_c2[k] = s;
    }
}
__global__ void k_zero() { if (threadIdx.x < N_BATCH) g_loss[threadIdx.x] = 0.f; }

// ---------------- CBup = codebook @ W_up^T (small fp32 SIMT GEMM) ----------------
static __device__ __forceinline__ unsigned long long bcast2(float x) {
    unsigned long long r; asm("mov.b64 %0, {%1, %1};" : "=l"(r) : "f"(x)); return r;
}
static __device__ __forceinline__ void fma2(unsigned long long& c, unsigned long long a,
                                            unsigned long long b) {
    asm("fma.rn.f32x2 %0, %1, %2, %0;" : "+l"(c) : "l"(a), "l"(b));
}
static __device__ __forceinline__ float2 unpack2(unsigned long long v) {
    float2 f;
    f.x = __uint_as_float((unsigned)(v & 0xffffffffull));
    f.y = __uint_as_float((unsigned)(v >> 32));
    return f;
}
__global__ void k_cbup(const float* __restrict__ A, const float* __restrict__ W) {
    __shared__ __align__(16) float As[32][68];
    __shared__ __align__(16) float Bs[32][68];
    const int m0 = blockIdx.x * 64, n0 = blockIdx.y * 64;
    const int tid = threadIdx.x, tx = tid & 15, ty = tid >> 4;
    unsigned long long acc[4][2];
    #pragma unroll
    for (int i = 0; i < 4; i++) { acc[i][0] = 0ull; acc[i][1] = 0ull; }
    for (int kk = 0; kk < D_EMBV; kk += 32) {
        #pragma unroll
        for (int i = 0; i < 8; i++) {
            int idx = tid + i * 256, r = idx >> 5, c = idx & 31;
            As[c][r] = A[(size_t)(m0 + r) * D_EMBV + kk + c];
            Bs[c][r] = W[(size_t)(n0 + r) * D_EMBV + kk + c];
        }
        __syncthreads();
        #pragma unroll
        for (int k = 0; k < 32; k++) {
            float4 av = *(const float4*)&As[k][ty * 4];
            ulonglong2 bv = *(const ulonglong2*)&Bs[k][tx * 4];
            unsigned long long a0 = bcast2(av.x), a1 = bcast2(av.y);
            unsigned long long a2 = bcast2(av.z), a3 = bcast2(av.w);
            fma2(acc[0][0], a0, bv.x); fma2(acc[0][1], a0, bv.y);
            fma2(acc[1][0], a1, bv.x); fma2(acc[1][1], a1, bv.y);
            fma2(acc[2][0], a2, bv.x); fma2(acc[2][1], a2, bv.y);
            fma2(acc[3][0], a3, bv.x); fma2(acc[3][1], a3, bv.y);
        }
        __syncthreads();
    }
    #pragma unroll
    for (int i = 0; i < 4; i++) {
        float2 p0 = unpack2(acc[i][0]), p1 = unpack2(acc[i][1]);
        *(float4*)&g_cbup[(size_t)(m0 + ty * 4 + i) * D_INV + n0 + tx * 4] =
            make_float4(p0.x, p0.y, p1.x, p1.y);
    }
}

// ---------------- k_down: zed = z_e @ Wd^T (2-way split, 3-pass HMMA) ------------
// buffer (40960B): Ah@0 Al@10240 Bh@20480 Bl@30720; x2 buffers. rows 80B.
#define KD_BUF  40960
#define KD_SMEM 81920
__global__ void __launch_bounds__(256, 1) k_down(const float* __restrict__ A,
                                                 float* __restrict__ C) {
    extern __shared__ __align__(16) char sm[];
    const unsigned sb = smem_u32(sm);
    const int tid = threadIdx.x, lane = tid & 31, wid = tid >> 5;
    const int wr = wid >> 1, wc = wid & 1;
    const int m0 = blockIdx.x * 128, n0 = blockIdx.y * 128;

    float acc[2][8][4];
    #pragma unroll
    for (int mi = 0; mi < 2; mi++)
        #pragma unroll
        for (int ni = 0; ni < 8; ni++)
            #pragma unroll
            for (int q = 0; q < 4; q++) acc[mi][ni][q] = 0.f;

    float4 areg[4];
    uint4  bh[2], bl[2];

    #pragma unroll
    for (int i = 0; i < 4; i++) {
        int j = tid + i * 256, r = j >> 3, c4 = j & 7;
        areg[i] = *(const float4*)&A[(size_t)(m0 + r) * D_INV + c4 * 4];
    }
    #pragma unroll
    for (int i = 0; i < 2; i++) {
        int j = tid + i * 256, r = j >> 2, c = j & 3;
        size_t src = (size_t)(n0 + r) * D_INV + c * 8;
        bh[i] = *(const uint4*)&g_wd_h[src];
        bl[i] = *(const uint4*)&g_wd_l[src];
    }
    {
        char* base = sm;
        #pragma unroll
        for (int i = 0; i < 4; i++) {
            int j = tid + i * 256, r = j >> 3, c4 = j & 7;
            uint2 h, l; split2_f4(areg[i], h, l);
            unsigned off = r * 80 + c4 * 8;
            *(uint2*)(base + off) = h;
            *(uint2*)(base + 10240 + off) = l;
        }
        #pragma unroll
        for (int i = 0; i < 2; i++) {
            int j = tid + i * 256, r = j >> 2, c = j & 3;
            unsigned off = r * 80 + c * 16;
            *(uint4*)(base + 20480 + off) = bh[i];
            *(uint4*)(base + 30720 + off) = bl[i];
        }
    }
    __syncthreads();

    #pragma unroll 1
    for (int ch = 0; ch < 16; ch++) {
        int nxt = ch + 1;
        if (nxt < 16) {
            #pragma unroll
            for (int i = 0; i < 4; i++) {
                int j = tid + i * 256, r = j >> 3, c4 = j & 7;
                areg[i] = *(const float4*)&A[(size_t)(m0 + r) * D_INV + nxt * 32 + c4 * 4];
            }
            #pragma unroll
            for (int i = 0; i < 2; i++) {
                int j = tid + i * 256, r = j >> 2, c = j & 3;
                size_t src = (size_t)(n0 + r) * D_INV + nxt * 32 + c * 8;
                bh[i] = *(const uint4*)&g_wd_h[src];
                bl[i] = *(const uint4*)&g_wd_l[src];
            }
        }
        {
            unsigned bufb = sb + (ch & 1) * KD_BUF;
            #pragma unroll
            for (int s = 0; s < 2; s++) {
                unsigned a_h[2][4], a_l[2][4];
                #pragma unroll
                for (int mi = 0; mi < 2; mi++) {
                    unsigned off = (wr * 32 + mi * 16 + (lane & 15)) * 80 +
                                   ((lane >> 4) << 4) + s * 32;
                    LDSM4(a_h[mi], bufb + off);
                    LDSM4(a_l[mi], bufb + 10240 + off);
                }
                #pragma unroll
                for (int nh = 0; nh < 2; nh++) {
                    unsigned b_h[4][2], b_l[4][2];
                    #pragma unroll
                    for (int p = 0; p < 2; p++) {
                        int np = nh * 2 + p;
                        unsigned off = (wc * 64 + np * 16 + (lane & 7) +
                                        ((lane >> 4) << 3)) * 80 +
                                       (((lane >> 3) & 1) << 4) + s * 32;
                        LDSM4B(b_h[p * 2], b_h[p * 2 + 1], bufb + 20480 + off);
                        LDSM4B(b_l[p * 2], b_l[p * 2 + 1], bufb + 30720 + off);
                    }
                    #pragma unroll
                    for (int mi = 0; mi < 2; mi++)
                        #pragma unroll
                        for (int k = 0; k < 4; k++)
                            MMA_B16(acc[mi][nh * 4 + k], a_h[mi], b_h[k]);
                    #pragma unroll
                    for (int mi = 0; mi < 2; mi++)
                        #pragma unroll
                        for (int k = 0; k < 4; k++)
                            MMA_B16(acc[mi][nh * 4 + k], a_l[mi], b_h[k]);
                    #pragma unroll
                    for (int mi = 0; mi < 2; mi++)
                        #pragma unroll
                        for (int k = 0; k < 4; k++)
                            MMA_B16(acc[mi][nh * 4 + k], a_h[mi], b_l[k]);
                }
            }
        }
        if (nxt < 16) {
            char* base = sm + (nxt & 1) * KD_BUF;
            #pragma unroll
            for (int i = 0; i < 4; i++) {
                int j = tid + i * 256, r = j >> 3, c4 = j & 7;
                uint2 h, l; split2_f4(areg[i], h, l);
                unsigned off = r * 80 + c4 * 8;
                *(uint2*)(base + off) = h;
                *(uint2*)(base + 10240 + off) = l;
            }
            #pragma unroll
            for (int i = 0; i < 2; i++) {
                int j = tid + i * 256, r = j >> 2, c = j & 3;
                unsigned off = r * 80 + c * 16;
                *(uint4*)(base + 20480 + off) = bh[i];
                *(uint4*)(base + 30720 + off) = bl[i];
            }
        }
        __syncthreads();
    }
    #pragma unroll
    for (int mi = 0; mi < 2; mi++)
        #pragma unroll
        for (int h = 0; h < 2; h++) {
            int row = m0 + wr * 32 + mi * 16 + h * 8 + (lane >> 2);
            #pragma unroll
            for (int ni = 0; ni < 8; ni++) {
                int col = n0 + wc * 64 + ni * 8 + 2 * (lane & 3);
                *(float2*)&C[(size_t)row * D_EMBV + col] =
                    make_float2(acc[mi][ni][h * 2], acc[mi][ni][h * 2 + 1]);
            }
        }
}

// ---------------- k_dist: fused dist GEMM + top2 argmin (bf16 2-split, 3-pass) ---
// smem: Ah chunks 0..7 @0 (8*10240) | Al @81920 | B bufs @163840 (2 * 20480)
// reduction @204800: m1(1024B) i1(1024B) m2(1024B) -> total 207872
#define DS_AL   81920
#define DS_BB   163840
#define DS_RED  204800
#define DS_SMEM 207872
__global__ void __launch_bounds__(256, 1) k_dist(const float* __restrict__ Z,
                                                 float* __restrict__ code_f) {
    extern __shared__ __align__(16) char sm[];
    const unsigned sb = smem_u32(sm);
    const int tid = threadIdx.x, lane = tid & 31, wid = tid >> 5;
    const int wr = wid >> 1, wc = wid & 1;
    const int m0 = blockIdx.x * 128;

    // resident A: split zed[m0..+128, 0..256) into 8 chunk tiles (hi/lo)
    #pragma unroll 4
    for (int i = 0; i < 32; i++) {
        int j = tid + i * 256, r = j >> 6, col4 = j & 63;
        int ch = col4 >> 3, c4 = col4 & 7;
        float4 v = *(const float4*)&Z[(size_t)(m0 + r) * D_EMBV + col4 * 4];
        uint2 h, l; split2_f4(v, h, l);
        unsigned off = ch * 10240 + r * 80 + c4 * 8;
        *(uint2*)(sm + off) = h;
        *(uint2*)(sm + DS_AL + off) = l;
    }

    float acc[2][8][4];
    #pragma unroll
    for (int mi = 0; mi < 2; mi++)
        #pragma unroll
        for (int ni = 0; ni < 8; ni++)
            #pragma unroll
            for (int q = 0; q < 4; q++) acc[mi][ni][q] = 0.f;

    float t1[4], t2[4]; int ti[4];
    #pragma unroll
    for (int s = 0; s < 4; s++) { t1[s] = 3.4e38f; t2[s] = 3.4e38f; ti[s] = 0; }

    uint4 pbh[2], pbl[2];
    #pragma unroll
    for (int i = 0; i < 2; i++) {
        int j = tid + i * 256, r = j >> 2, c = j & 3;
        size_t src = (size_t)r * D_EMBV + c * 8;
        pbh[i] = *(const uint4*)&g_cb_h[src];
        pbl[i] = *(const uint4*)&g_cb_l[src];
    }
    {
        char* base = sm + DS_BB;
        #pragma unroll
        for (int i = 0; i < 2; i++) {
            int j = tid + i * 256, r = j >> 2, c = j & 3;
            unsigned off = r * 80 + c * 16;
            *(uint4*)(base + off) = pbh[i];
            *(uint4*)(base + 10240 + off) = pbl[i];
        }
    }
    __syncthreads();

    #pragma unroll 1
    for (int it = 0; it < 64; it++) {
        int nt = it >> 3, ch = it & 7;
        int nxt = it + 1;
        if (nxt < 64) {
            int nnt = nxt >> 3, nch = nxt & 7;
            #pragma unroll
            for (int i = 0; i < 2; i++) {
                int j = tid + i * 256, r = j >> 2, c = j & 3;
                size_t src = (size_t)(nnt * 128 + r) * D_EMBV + nch * 32 + c * 8;
                pbh[i] = *(const uint4*)&g_cb_h[src];
                pbl[i] = *(const uint4*)&g_cb_l[src];
            }
        }
        {
            unsigned abase = sb + ch * 10240;
            unsigned bbase = sb + DS_BB + (it & 1) * 20480;
            #pragma unroll
            for (int s = 0; s < 2; s++) {
                unsigned a_h[2][4], a_l[2][4];
                #pragma unroll
                for (int mi = 0; mi < 2; mi++) {
                    unsigned off = (wr * 32 + mi * 16 + (lane & 15)) * 80 +
                                   ((lane >> 4) << 4) + s * 32;
                    LDSM4(a_h[mi], abase + off);
                    LDSM4(a_l[mi], abase + DS_AL + off);
                }
                #pragma unroll
                for (int nh = 0; nh < 2; nh++) {
                    unsigned b_h[4][2], b_l[4][2];
                    #pragma unroll
                    for (int p = 0; p < 2; p++) {
                        int np = nh * 2 + p;
                        unsigned off = (wc * 64 + np * 16 + (lane & 7) +
                                        ((lane >> 4) << 3)) * 80 +
                                       (((lane >> 3) & 1) << 4) + s * 32;
                        LDSM4B(b_h[p * 2], b_h[p * 2 + 1], bbase + off);
                        LDSM4B(b_l[p * 2], b_l[p * 2 + 1], bbase + 10240 + off);
                    }
                    #pragma unroll
                    for (int mi = 0; mi < 2; mi++)
                        #pragma unroll
                        for (int k = 0; k < 4; k++)
                            MMA_B16(acc[mi][nh * 4 + k], a_h[mi], b_h[k]);
                    #pragma unroll
                    for (int mi = 0; mi < 2; mi++)
                        #pragma unroll
                        for (int k = 0; k < 4; k++)
                            MMA_B16(acc[mi][nh * 4 + k], a_l[mi], b_h[k]);
                    #pragma unroll
                    for (int mi = 0; mi < 2; mi++)
                        #pragma unroll
                        for (int k = 0; k < 4; k++)
                            MMA_B16(acc[mi][nh * 4 + k], a_h[mi], b_l[k]);
                }
            }
        }
        if (ch == 7) {
            #pragma unroll
            for (int ni = 0; ni < 8; ni++)
                #pragma unroll
                for (int cc = 0; cc < 2; cc++) {
                    int g = nt * 128 + wc * 64 + ni * 8 + 2 * (lane & 3) + cc;
                    float c2v = __ldg(&g_c2[g]);
                    #pragma unroll
                    for (int mi = 0; mi < 2; mi++)
                        #pragma unroll
                        for (int h = 0; h < 2; h++) {
                            int slot = mi * 2 + h;
                            float d = c2v - 2.f * acc[mi][ni][h * 2 + cc];
                            if (d < t1[slot]) { t2[slot] = t1[slot]; t1[slot] = d; ti[slot] = g; }
                            else if (d < t2[slot]) { t2[slot] = d; }
                        }
                }
            #pragma unroll
            for (int mi = 0; mi < 2; mi++)
                #pragma unroll
                for (int ni = 0; ni < 8; ni++)
                    #pragma unroll
                    for (int q = 0; q < 4; q++) acc[mi][ni][q] = 0.f;
        }
        if (nxt < 64) {
            char* base = sm + DS_BB + (nxt & 1) * 20480;
            #pragma unroll
            for (int i = 0; i < 2; i++) {
                int j = tid + i * 256, r = j >> 2, c = j & 3;
                unsigned off = r * 80 + c * 16;
                *(uint4*)(base + off) = pbh[i];
                *(uint4*)(base + 10240 + off) = pbl[i];
            }
        }
        __syncthreads();
    }

    // quad reduce (lanes sharing lane>>2 hold the same rows)
    #pragma unroll
    for (int s = 0; s < 4; s++) {
        #pragma unroll
        for (int off = 1; off <= 2; off <<= 1) {
            float o1 = __shfl_xor_sync(0xffffffffu, t1[s], off);
            float o2 = __shfl_xor_sync(0xffffffffu, t2[s], off);
            int oi = __shfl_xor_sync(0xffffffffu, ti[s], off);
            bool takeo = (o1 < t1[s]) || (o1 == t1[s] && oi < ti[s]);
            float nm2 = takeo ? fminf(t1[s], o2) : fminf(t2[s], o1);
            if (takeo) { t1[s] = o1; ti[s] = oi; }
            t2[s] = nm2;
        }
    }
    float* red_m1 = (float*)(sm + DS_RED);
    int*   red_i1 = (int*)(sm + DS_RED + 1024);
    float* red_m2 = (float*)(sm + DS_RED + 2048);
    if ((lane & 3) == 0) {
        #pragma unroll
        for (int mi = 0; mi < 2; mi++)
            #pragma unroll
            for (int h = 0; h < 2; h++) {
                int s = mi * 2 + h;
                int row = wr * 32 + mi * 16 + h * 8 + (lane >> 2);
                red_m1[row * 2 + wc] = t1[s];
                red_i1[row * 2 + wc] = ti[s];
                red_m2[row * 2 + wc] = t2[s];
            }
    }
    __syncthreads();
    if (tid < 128) {
        float m1a = red_m1[tid * 2], m2a = red_m2[tid * 2];
        int   i1a = red_i1[tid * 2];
        float m1b = red_m1[tid * 2 + 1], m2b = red_m2[tid * 2 + 1];
        int   i1b = red_i1[tid * 2 + 1];
        bool takeb = (m1b < m1a) || (m1b == m1a && i1b < i1a);
        float m1c = takeb ? m1b : m1a;
        int   i1c = takeb ? i1b : i1a;
        float m2c = takeb ? fminf(m1a, m2b) : fminf(m2a, m1b);
        int t = m0 + tid;
        g_code[t] = i1c;
        code_f[t] = (float)i1c;
        if (m2c - m1c < 0.02f) {
            int pos = atomicAdd(&g_cnt_f, 1);
            g_list_f[pos] = t;
        }
    }
}

// ---------------- exact fp32 re-decide: one BLOCK per flagged token --------------
__global__ void __launch_bounds__(256, 1) k_fix(const float* __restrict__ Z,
                                                const float* __restrict__ CB,
                                                float* __restrict__ code_f) {
    __shared__ float zed[D_EMBV];
    __shared__ float bm[256];
    __shared__ int   bix[256];
    const int tid = threadIdx.x;
    const int cnt = g_cnt_f;
    for (int i = blockIdx.x; i < cnt; i += gridDim.x) {
        int t = g_list_f[i];
        zed[tid] = Z[(size_t)t * D_EMBV + tid];
        __syncthreads();
        float best = 3.4e38f; int bi = 0x7fffffff;
        #pragma unroll 1
        for (int k = tid; k < K_CODES; k += 256) {
            const float* cr = CB + (size_t)k * D_EMBV;
            float dot = 0.f;
            #pragma unroll 8
            for (int e = 0; e < D_EMBV; e++) dot += zed[e] * cr[e];
            float d = g_c2[k] - 2.f * dot;
            if (d < best) { best = d; bi = k; }   // k increasing: first-index ties kept
        }
        bm[tid] = best; bix[tid] = bi;
        __syncthreads();
        for (int off = 128; off > 0; off >>= 1) {
            if (tid < off) {
                float o = bm[tid + off]; int oi = bix[tid + off];
                if (o < bm[tid] || (o == bm[tid] && oi < bix[tid])) {
                    bm[tid] = o; bix[tid] = oi;
                }
            }
            __syncthreads();
        }
        if (tid == 0) { g_code[t] = bix[0]; code_f[t] = (float)bix[0]; }
        __syncthreads();
    }
}

// ---------------- gather: zq[t] = CBup[code[t]] ----------------------------------
__global__ void k_gather(float* __restrict__ ZQ) {
    int idx = blockIdx.x * blockDim.x + threadIdx.x;
    int t = idx >> 7, j = idx & 127;
    int code = g_code[t];
    ((float4*)ZQ)[(size_t)t * 128 + j] = ((const float4*)g_cbup)[(size_t)code * 128 + j];
}

// ---------------- per-batch VQ losses --------------------------------------------
__global__ void k_loss(const float* __restrict__ Z, const float* __restrict__ CB) {
    int lane = threadIdx.x & 31;
    int t = (blockIdx.x * blockDim.x + threadIdx.x) >> 5;
    int code = g_code[t];
    float s = 0.f;
    #pragma unroll
    for (int i = 0; i < 8; i++) {
        int e = lane + 32 * i;
        float d = Z[(size_t)t * D_EMBV + e] - CB[(size_t)code * D_EMBV + e];
        s += d * d;
    }
    #pragma unroll
    for (int o = 16; o > 0; o >>= 1) s += __shfl_xor_sync(0xffffffffu, s, o);
    if (lane == 0) atomicAdd(&g_loss[t >> 12], s);
}
__global__ void k_finish(float* __restrict__ oc, float* __restrict__ ob) {
    int i = threadIdx.x;
    if (i < N_BATCH) {
        float v = g_loss[i] * (1.0f / ((float)T_SEQ * (float)D_EMBV));
        oc[i] = v; ob[i] = v;
    }
}

// ---------------- launcher --------------------------------------------------------
extern "C" void kernel_launch(void* const* d_in, const int* in_sizes, int n_in,
                              void* d_out, int out_size) {
    const float* z_e    = (const float*)d_in[0];
    const float* cb     = (const float*)d_in[1];
    const float* w_down = (const float*)d_in[2];
    const float* w_up   = (const float*)d_in[3];

    float* out     = (float*)d_out;
    float* zq      = out;
    float* zed     = out + (size_t)BT_TOK * D_INV;
    float* codef   = out + (size_t)BT_TOK * (D_INV + D_EMBV);
    float* lcommit = codef + BT_TOK;
    float* lcb     = lcommit + N_BATCH;

    cudaFuncSetAttribute(k_down, cudaFuncAttributeMaxDynamicSharedMemorySize, KD_SMEM);
    cudaFuncSetAttribute(k_dist, cudaFuncAttributeMaxDynamicSharedMemorySize, DS_SMEM);

    // k_dist stays the 4th launch for ncu visibility
    k_prep<<<(D_EMBV * D_INV + K_CODES * D_EMBV + 255) / 256, 256>>>(w_down, cb);
    k_c2<<<(K_CODES + 255) / 256, 256>>>(cb);
    k_down<<<dim3(BT_TOK / 128, 2), 256, KD_SMEM>>>(z_e, zed);
    k_dist<<<BT_TOK / 128, 256, DS_SMEM>>>(zed, codef);
    k_cbup<<<dim3(K_CODES / 64, D_INV / 64), 256>>>(cb, w_up);
    k_zero<<<1, 32>>>();
    k_fix<<<512, 256>>>(zed, cb, codef);
    k_gather<<<(BT_TOK * 128) / 256, 256>>>(zq);
    k_loss<<<BT_TOK / 8, 256>>>(zed, cb);
    k_finish<<<1, 32>>>(lcommit, lcb);
}

// round 17
// speedup vs baseline: 2.1155x; 1.1005x over previous
#include <cuda_runtime.h>
#include <cuda_bf16.h>

#define BT_TOK  65536
#define D_INV   512
#define D_EMBV  256
#define K_CODES 1024
#define N_BATCH 16
#define T_SEQ   4096

// ---------------- device scratch ---------------------------------------------
__device__ int           g_code[BT_TOK];
__device__ int           g_cnt_f;
__device__ int           g_list_f[BT_TOK];
__device__ float         g_c2[K_CODES];
__device__ float         g_loss[N_BATCH];
__device__ __nv_bfloat16 g_wd_h[D_EMBV * D_INV];
__device__ __nv_bfloat16 g_wd_l[D_EMBV * D_INV];
__device__ __nv_bfloat16 g_cb_h[K_CODES * D_EMBV];
__device__ __nv_bfloat16 g_cb_l[K_CODES * D_EMBV];
__device__ float         g_cbup[K_CODES * D_INV];

// ---------------- helpers -------------------------------------------------------
static __device__ __forceinline__ unsigned smem_u32(const void* p) {
    unsigned a;
    asm("{ .reg .u64 t; cvta.to.shared.u64 t, %1; cvt.u32.u64 %0, t; }"
        : "=r"(a) : "l"(p));
    return a;
}

#define LDSM4(d, addr) \
    asm volatile("ldmatrix.sync.aligned.m8n8.x4.shared.b16 {%0,%1,%2,%3}, [%4];" \
        : "=r"((d)[0]), "=r"((d)[1]), "=r"((d)[2]), "=r"((d)[3]) : "r"(addr))

#define LDSM4B(b0, b1, addr) \
    asm volatile("ldmatrix.sync.aligned.m8n8.x4.shared.b16 {%0,%1,%2,%3}, [%4];" \
        : "=r"((b0)[0]), "=r"((b0)[1]), "=r"((b1)[0]), "=r"((b1)[1]) : "r"(addr))

#define MMA_B16(c, a, b) \
    asm volatile("mma.sync.aligned.m16n8k16.row.col.f32.bf16.bf16.f32 " \
        "{%0,%1,%2,%3},{%4,%5,%6,%7},{%8,%9},{%0,%1,%2,%3};" \
        : "+f"((c)[0]), "+f"((c)[1]), "+f"((c)[2]), "+f"((c)[3]) \
        : "r"((a)[0]), "r"((a)[1]), "r"((a)[2]), "r"((a)[3]), "r"((b)[0]), "r"((b)[1]))

static __device__ __forceinline__ unsigned pack_bf2(float x, float y) {
    __nv_bfloat162 t = __float22bfloat162_rn(make_float2(x, y));
    return *(unsigned*)&t;
}

// 2-way split: v -> hi, lo  (each uint2 = 4 bf16)
static __device__ __forceinline__ void split2_f4(float4 v, uint2& h, uint2& l) {
    __nv_bfloat162 h01 = __float22bfloat162_rn(make_float2(v.x, v.y));
    __nv_bfloat162 h23 = __float22bfloat162_rn(make_float2(v.z, v.w));
    float r0 = v.x - __bfloat162float(h01.x);
    float r1 = v.y - __bfloat162float(h01.y);
    float r2 = v.z - __bfloat162float(h23.x);
    float r3 = v.w - __bfloat162float(h23.y);
    h.x = *(unsigned*)&h01; h.y = *(unsigned*)&h23;
    l.x = pack_bf2(r0, r1); l.y = pack_bf2(r2, r3);
}

// ---------------- prep kernels ---------------------------------------------------
__global__ void k_prep(const float* __restrict__ wd, const float* __restrict__ cb) {
    int i = blockIdx.x * blockDim.x + threadIdx.x;
    if (i < D_EMBV * D_INV) {
        float x = wd[i];
        __nv_bfloat16 h = __float2bfloat16(x);
        g_wd_h[i] = h;
        g_wd_l[i] = __float2bfloat16(x - __bfloat162float(h));
    }
    int j = i - D_EMBV * D_INV;
    if (j >= 0 && j < K_CODES * D_EMBV) {
        float x = cb[j];
        __nv_bfloat16 h = __float2bfloat16(x);
        g_cb_h[j] = h;
        g_cb_l[j] = __float2bfloat16(x - __bfloat162float(h));
    }
}
__global__ void k_c2(const float* __restrict__ CB) {
    int k = blockIdx.x * blockDim.x + threadIdx.x;
    if (k == 0) g_cnt_f = 0;
    if (k < K_CODES) {
        const float* row = CB + (size_t)k * D_EMBV;
        float s = 0.f;
        #pragma unroll 8
        for (int e = 0; e < D_EMBV; e++) s += row[e] * row[e];
        g_c2[k] = s;
    }
}
__global__ void k_zero() { if (threadIdx.x < N_BATCH) g_loss[threadIdx.x] = 0.f; }

// ---------------- CBup = codebook @ W_up^T (small fp32 SIMT GEMM) ----------------
static __device__ __forceinline__ unsigned long long bcast2(float x) {
    unsigned long long r; asm("mov.b64 %0, {%1, %1};" : "=l"(r) : "f"(x)); return r;
}
static __device__ __forceinline__ void fma2(unsigned long long& c, unsigned long long a,
                                            unsigned long long b) {
    asm("fma.rn.f32x2 %0, %1, %2, %0;" : "+l"(c) : "l"(a), "l"(b));
}
static __device__ __forceinline__ float2 unpack2(unsigned long long v) {
    float2 f;
    f.x = __uint_as_float((unsigned)(v & 0xffffffffull));
    f.y = __uint_as_float((unsigned)(v >> 32));
    return f;
}
__global__ void k_cbup(const float* __restrict__ A, const float* __restrict__ W) {
    __shared__ __align__(16) float As[32][68];
    __shared__ __align__(16) float Bs[32][68];
    const int m0 = blockIdx.x * 64, n0 = blockIdx.y * 64;
    const int tid = threadIdx.x, tx = tid & 15, ty = tid >> 4;
    unsigned long long acc[4][2];
    #pragma unroll
    for (int i = 0; i < 4; i++) { acc[i][0] = 0ull; acc[i][1] = 0ull; }
    for (int kk = 0; kk < D_EMBV; kk += 32) {
        #pragma unroll
        for (int i = 0; i < 8; i++) {
            int idx = tid + i * 256, r = idx >> 5, c = idx & 31;
            As[c][r] = A[(size_t)(m0 + r) * D_EMBV + kk + c];
            Bs[c][r] = W[(size_t)(n0 + r) * D_EMBV + kk + c];
        }
        __syncthreads();
        #pragma unroll
        for (int k = 0; k < 32; k++) {
            float4 av = *(const float4*)&As[k][ty * 4];
            ulonglong2 bv = *(const ulonglong2*)&Bs[k][tx * 4];
            unsigned long long a0 = bcast2(av.x), a1 = bcast2(av.y);
            unsigned long long a2 = bcast2(av.z), a3 = bcast2(av.w);
            fma2(acc[0][0], a0, bv.x); fma2(acc[0][1], a0, bv.y);
            fma2(acc[1][0], a1, bv.x); fma2(acc[1][1], a1, bv.y);
            fma2(acc[2][0], a2, bv.x); fma2(acc[2][1], a2, bv.y);
            fma2(acc[3][0], a3, bv.x); fma2(acc[3][1], a3, bv.y);
        }
        __syncthreads();
    }
    #pragma unroll
    for (int i = 0; i < 4; i++) {
        float2 p0 = unpack2(acc[i][0]), p1 = unpack2(acc[i][1]);
        *(float4*)&g_cbup[(size_t)(m0 + ty * 4 + i) * D_INV + n0 + tx * 4] =
            make_float4(p0.x, p0.y, p1.x, p1.y);
    }
}

// ---------------- k_down: zed = z_e @ Wd^T (512 thr, 2-way split, 3-pass) --------
// buffer (40960B): Ah@0 Al@10240 Bh@20480 Bl@30720; x2 buffers. rows 80B.
#define KD_BUF  40960
#define KD_SMEM 81920
__global__ void __launch_bounds__(512, 1) k_down(const float* __restrict__ A,
                                                 float* __restrict__ C) {
    extern __shared__ __align__(16) char sm[];
    const unsigned sb = smem_u32(sm);
    const int tid = threadIdx.x, lane = tid & 31, wid = tid >> 5;
    const int wr = wid >> 2, wc = wid & 3;
    const int m0 = blockIdx.x * 128, n0 = blockIdx.y * 128;

    float acc[2][4][4];
    #pragma unroll
    for (int mi = 0; mi < 2; mi++)
        #pragma unroll
        for (int nj = 0; nj < 4; nj++)
            #pragma unroll
            for (int q = 0; q < 4; q++) acc[mi][nj][q] = 0.f;

    const int br = tid >> 2, bc = tid & 3;
    float4 areg[2];
    uint4  bh, bl;

    #pragma unroll
    for (int i = 0; i < 2; i++) {
        int j = tid + i * 512, r = j >> 3, c4 = j & 7;
        areg[i] = *(const float4*)&A[(size_t)(m0 + r) * D_INV + c4 * 4];
    }
    bh = *(const uint4*)&g_wd_h[(size_t)(n0 + br) * D_INV + bc * 8];
    bl = *(const uint4*)&g_wd_l[(size_t)(n0 + br) * D_INV + bc * 8];
    {
        char* base = sm;
        #pragma unroll
        for (int i = 0; i < 2; i++) {
            int j = tid + i * 512, r = j >> 3, c4 = j & 7;
            uint2 h, l; split2_f4(areg[i], h, l);
            unsigned off = r * 80 + c4 * 8;
            *(uint2*)(base + off) = h;
            *(uint2*)(base + 10240 + off) = l;
        }
        unsigned off = br * 80 + bc * 16;
        *(uint4*)(base + 20480 + off) = bh;
        *(uint4*)(base + 30720 + off) = bl;
    }
    __syncthreads();

    #pragma unroll 1
    for (int ch = 0; ch < 16; ch++) {
        int nxt = ch + 1;
        if (nxt < 16) {
            #pragma unroll
            for (int i = 0; i < 2; i++) {
                int j = tid + i * 512, r = j >> 3, c4 = j & 7;
                areg[i] = *(const float4*)&A[(size_t)(m0 + r) * D_INV + nxt * 32 + c4 * 4];
            }
            bh = *(const uint4*)&g_wd_h[(size_t)(n0 + br) * D_INV + nxt * 32 + bc * 8];
            bl = *(const uint4*)&g_wd_l[(size_t)(n0 + br) * D_INV + nxt * 32 + bc * 8];
        }
        {
            unsigned bufb = sb + (ch & 1) * KD_BUF;
            #pragma unroll
            for (int s = 0; s < 2; s++) {
                unsigned a_h[2][4], a_l[2][4];
                #pragma unroll
                for (int mi = 0; mi < 2; mi++) {
                    unsigned off = (wr * 32 + mi * 16 + (lane & 15)) * 80 +
                                   ((lane >> 4) << 4) + s * 32;
                    LDSM4(a_h[mi], bufb + off);
                    LDSM4(a_l[mi], bufb + 10240 + off);
                }
                unsigned b_h[4][2], b_l[4][2];
                #pragma unroll
                for (int p = 0; p < 2; p++) {
                    unsigned off = (wc * 32 + p * 16 + (lane & 7) +
                                    ((lane >> 4) << 3)) * 80 +
                                   (((lane >> 3) & 1) << 4) + s * 32;
                    LDSM4B(b_h[p * 2], b_h[p * 2 + 1], bufb + 20480 + off);
                    LDSM4B(b_l[p * 2], b_l[p * 2 + 1], bufb + 30720 + off);
                }
                #pragma unroll
                for (int mi = 0; mi < 2; mi++)
                    #pragma unroll
                    for (int k = 0; k < 4; k++) MMA_B16(acc[mi][k], a_h[mi], b_h[k]);
                #pragma unroll
                for (int mi = 0; mi < 2; mi++)
                    #pragma unroll
                    for (int k = 0; k < 4; k++) MMA_B16(acc[mi][k], a_l[mi], b_h[k]);
                #pragma unroll
                for (int mi = 0; mi < 2; mi++)
                    #pragma unroll
                    for (int k = 0; k < 4; k++) MMA_B16(acc[mi][k], a_h[mi], b_l[k]);
            }
        }
        if (nxt < 16) {
            char* base = sm + (nxt & 1) * KD_BUF;
            #pragma unroll
            for (int i = 0; i < 2; i++) {
                int j = tid + i * 512, r = j >> 3, c4 = j & 7;
                uint2 h, l; split2_f4(areg[i], h, l);
                unsigned off = r * 80 + c4 * 8;
                *(uint2*)(base + off) = h;
                *(uint2*)(base + 10240 + off) = l;
            }
            unsigned off = br * 80 + bc * 16;
            *(uint4*)(base + 20480 + off) = bh;
            *(uint4*)(base + 30720 + off) = bl;
        }
        __syncthreads();
    }
    #pragma unroll
    for (int mi = 0; mi < 2; mi++)
        #pragma unroll
        for (int h = 0; h < 2; h++) {
            int row = m0 + wr * 32 + mi * 16 + h * 8 + (lane >> 2);
            #pragma unroll
            for (int nj = 0; nj < 4; nj++) {
                int col = n0 + wc * 32 + nj * 8 + 2 * (lane & 3);
                *(float2*)&C[(size_t)row * D_EMBV + col] =
                    make_float2(acc[mi][nj][h * 2], acc[mi][nj][h * 2 + 1]);
            }
        }
}

// ---------------- k_dist: 512 thr, 3-pass, A-resident, top2 + list ---------------
// smem: Ah chunks 0..7 @0 (81920) | Al @81920 | B bufs @163840 (2*20480)
// red @204800: m1(2048) i1(2048) m2(2048) -> 210944 total
#define DS_AL   81920
#define DS_BB   163840
#define DS_RED  204800
#define DS_SMEM 210944
__global__ void __launch_bounds__(512, 1) k_dist(const float* __restrict__ Z,
                                                 float* __restrict__ code_f) {
    extern __shared__ __align__(16) char sm[];
    const unsigned sb = smem_u32(sm);
    const int tid = threadIdx.x, lane = tid & 31, wid = tid >> 5;
    const int wr = wid >> 2, wc = wid & 3;
    const int m0 = blockIdx.x * 128;

    // resident A: split zed[m0..+128, 0..256) into 8 chunk tiles (hi/lo)
    #pragma unroll 4
    for (int i = 0; i < 16; i++) {
        int j = tid + i * 512, r = j >> 6, col4 = j & 63;
        int ch = col4 >> 3, c4 = col4 & 7;
        float4 v = *(const float4*)&Z[(size_t)(m0 + r) * D_EMBV + col4 * 4];
        uint2 h, l; split2_f4(v, h, l);
        unsigned off = ch * 10240 + r * 80 + c4 * 8;
        *(uint2*)(sm + off) = h;
        *(uint2*)(sm + DS_AL + off) = l;
    }

    float acc[2][4][4];
    #pragma unroll
    for (int mi = 0; mi < 2; mi++)
        #pragma unroll
        for (int nj = 0; nj < 4; nj++)
            #pragma unroll
            for (int q = 0; q < 4; q++) acc[mi][nj][q] = 0.f;

    float t1[4], t2[4]; int ti[4];
    #pragma unroll
    for (int s = 0; s < 4; s++) { t1[s] = 3.4e38f; t2[s] = 3.4e38f; ti[s] = 0; }

    const int br = tid >> 2, bc = tid & 3;
    uint4 pbh, pbl;
    pbh = *(const uint4*)&g_cb_h[(size_t)br * D_EMBV + bc * 8];
    pbl = *(const uint4*)&g_cb_l[(size_t)br * D_EMBV + bc * 8];
    {
        char* base = sm + DS_BB;
        unsigned off = br * 80 + bc * 16;
        *(uint4*)(base + off) = pbh;
        *(uint4*)(base + 10240 + off) = pbl;
    }
    __syncthreads();

    #pragma unroll 1
    for (int it = 0; it < 64; it++) {
        int nt = it >> 3, ch = it & 7;
        int nxt = it + 1;
        if (nxt < 64) {
            int nnt = nxt >> 3, nch = nxt & 7;
            size_t src = (size_t)(nnt * 128 + br) * D_EMBV + nch * 32 + bc * 8;
            pbh = *(const uint4*)&g_cb_h[src];
            pbl = *(const uint4*)&g_cb_l[src];
        }
        {
            unsigned abase = sb + ch * 10240;
            unsigned bbase = sb + DS_BB + (it & 1) * 20480;
            #pragma unroll
            for (int s = 0; s < 2; s++) {
                unsigned a_h[2][4], a_l[2][4];
                #pragma unroll
                for (int mi = 0; mi < 2; mi++) {
                    unsigned off = (wr * 32 + mi * 16 + (lane & 15)) * 80 +
                                   ((lane >> 4) << 4) + s * 32;
                    LDSM4(a_h[mi], abase + off);
                    LDSM4(a_l[mi], abase + DS_AL + off);
                }
                unsigned b_h[4][2], b_l[4][2];
                #pragma unroll
                for (int p = 0; p < 2; p++) {
                    unsigned off = (wc * 32 + p * 16 + (lane & 7) +
                                    ((lane >> 4) << 3)) * 80 +
                                   (((lane >> 3) & 1) << 4) + s * 32;
                    LDSM4B(b_h[p * 2], b_h[p * 2 + 1], bbase + off);
                    LDSM4B(b_l[p * 2], b_l[p * 2 + 1], bbase + 10240 + off);
                }
                #pragma unroll
                for (int mi = 0; mi < 2; mi++)
                    #pragma unroll
                    for (int k = 0; k < 4; k++) MMA_B16(acc[mi][k], a_h[mi], b_h[k]);
                #pragma unroll
                for (int mi = 0; mi < 2; mi++)
                    #pragma unroll
                    for (int k = 0; k < 4; k++) MMA_B16(acc[mi][k], a_l[mi], b_h[k]);
                #pragma unroll
                for (int mi = 0; mi < 2; mi++)
                    #pragma unroll
                    for (int k = 0; k < 4; k++) MMA_B16(acc[mi][k], a_h[mi], b_l[k]);
            }
        }
        if (ch == 7) {
            #pragma unroll
            for (int nj = 0; nj < 4; nj++)
                #pragma unroll
                for (int cc = 0; cc < 2; cc++) {
                    int g = nt * 128 + wc * 32 + nj * 8 + 2 * (lane & 3) + cc;
                    float c2v = __ldg(&g_c2[g]);
                    #pragma unroll
                    for (int mi = 0; mi < 2; mi++)
                        #pragma unroll
                        for (int h = 0; h < 2; h++) {
                            int slot = mi * 2 + h;
                            float d = c2v - 2.f * acc[mi][nj][h * 2 + cc];
                            if (d < t1[slot]) { t2[slot] = t1[slot]; t1[slot] = d; ti[slot] = g; }
                            else if (d < t2[slot]) { t2[slot] = d; }
                        }
                }
            #pragma unroll
            for (int mi = 0; mi < 2; mi++)
                #pragma unroll
                for (int nj = 0; nj < 4; nj++)
                    #pragma unroll
                    for (int q = 0; q < 4; q++) acc[mi][nj][q] = 0.f;
        }
        if (nxt < 64) {
            char* base = sm + DS_BB + (nxt & 1) * 20480;
            unsigned off = br * 80 + bc * 16;
            *(uint4*)(base + off) = pbh;
            *(uint4*)(base + 10240 + off) = pbl;
        }
        __syncthreads();
    }

    // quad reduce (lanes 4k..4k+3 share rows)
    #pragma unroll
    for (int s = 0; s < 4; s++) {
        #pragma unroll
        for (int off = 1; off <= 2; off <<= 1) {
            float o1 = __shfl_xor_sync(0xffffffffu, t1[s], off);
            float o2 = __shfl_xor_sync(0xffffffffu, t2[s], off);
            int oi = __shfl_xor_sync(0xffffffffu, ti[s], off);
            bool takeo = (o1 < t1[s]) || (o1 == t1[s] && oi < ti[s]);
            float nm2 = takeo ? fminf(t1[s], o2) : fminf(t2[s], o1);
            if (takeo) { t1[s] = o1; ti[s] = oi; }
            t2[s] = nm2;
        }
    }
    float* red_m1 = (float*)(sm + DS_RED);
    int*   red_i1 = (int*)(sm + DS_RED + 2048);
    float* red_m2 = (float*)(sm + DS_RED + 4096);
    if ((lane & 3) == 0) {
        #pragma unroll
        for (int mi = 0; mi < 2; mi++)
            #pragma unroll
            for (int h = 0; h < 2; h++) {
                int s = mi * 2 + h;
                int row = wr * 32 + mi * 16 + h * 8 + (lane >> 2);
                red_m1[row * 4 + wc] = t1[s];
                red_i1[row * 4 + wc] = ti[s];
                red_m2[row * 4 + wc] = t2[s];
            }
    }
    __syncthreads();
    if (tid < 128) {
        float m1 = red_m1[tid * 4]; int i1 = red_i1[tid * 4]; float m2 = red_m2[tid * 4];
        #pragma unroll
        for (int x = 1; x < 4; x++) {
            float n1 = red_m1[tid * 4 + x], n2 = red_m2[tid * 4 + x];
            int ni = red_i1[tid * 4 + x];
            bool take = (n1 < m1) || (n1 == m1 && ni < i1);
            float nm2 = take ? fminf(m1, n2) : fminf(m2, n1);
            if (take) { m1 = n1; i1 = ni; }
            m2 = nm2;
        }
        int t = m0 + tid;
        g_code[t] = i1;
        code_f[t] = (float)i1;
        if (m2 - m1 < 0.02f) {
            int pos = atomicAdd(&g_cnt_f, 1);
            g_list_f[pos] = t;
        }
    }
}

// ---------------- exact fp32 re-decide: one BLOCK per flagged token --------------
__global__ void __launch_bounds__(256, 1) k_fix(const float* __restrict__ Z,
                                                const float* __restrict__ CB,
                                                float* __restrict__ code_f) {
    __shared__ float zed[D_EMBV];
    __shared__ float bm[256];
    __shared__ int   bix[256];
    const int tid = threadIdx.x;
    const int cnt = g_cnt_f;
    for (int i = blockIdx.x; i < cnt; i += gridDim.x) {
        int t = g_list_f[i];
        zed[tid] = Z[(size_t)t * D_EMBV + tid];
        __syncthreads();
        float best = 3.4e38f; int bi = 0x7fffffff;
        #pragma unroll 1
        for (int k = tid; k < K_CODES; k += 256) {
            const float* cr = CB + (size_t)k * D_EMBV;
            float dot = 0.f;
            #pragma unroll 8
            for (int e = 0; e < D_EMBV; e++) dot += zed[e] * cr[e];
            float d = g_c2[k] - 2.f * dot;
            if (d < best) { best = d; bi = k; }
        }
        bm[tid] = best; bix[tid] = bi;
        __syncthreads();
        for (int off = 128; off > 0; off >>= 1) {
            if (tid < off) {
                float o = bm[tid + off]; int oi = bix[tid + off];
                if (o < bm[tid] || (o == bm[tid] && oi < bix[tid])) {
                    bm[tid] = o; bix[tid] = oi;
                }
            }
            __syncthreads();
        }
        if (tid == 0) { g_code[t] = bix[0]; code_f[t] = (float)bix[0]; }
        __syncthreads();
    }
}

// ---------------- gather: zq[t] = CBup[code[t]] ----------------------------------
__global__ void k_gather(float* __restrict__ ZQ) {
    int idx = blockIdx.x * blockDim.x + threadIdx.x;
    int t = idx >> 7, j = idx & 127;
    int code = g_code[t];
    ((float4*)ZQ)[(size_t)t * 128 + j] = ((const float4*)g_cbup)[(size_t)code * 128 + j];
}

// ---------------- per-batch VQ losses (block-level atomic) ------------------------
__global__ void k_loss(const float* __restrict__ Z, const float* __restrict__ CB) {
    __shared__ float part[8];
    int lane = threadIdx.x & 31, wid = threadIdx.x >> 5;
    int t = blockIdx.x * 8 + wid;
    int code = g_code[t];
    float s = 0.f;
    #pragma unroll
    for (int i = 0; i < 8; i++) {
        int e = lane + 32 * i;
        float d = Z[(size_t)t * D_EMBV + e] - CB[(size_t)code * D_EMBV + e];
        s += d * d;
    }
    #pragma unroll
    for (int o = 16; o > 0; o >>= 1) s += __shfl_xor_sync(0xffffffffu, s, o);
    if (lane == 0) part[wid] = s;
    __syncthreads();
    if (threadIdx.x == 0) {
        float tot = 0.f;
        #pragma unroll
        for (int i = 0; i < 8; i++) tot += part[i];
        atomicAdd(&g_loss[t >> 12], tot);   // all 8 tokens share one batch (4096 % 8 == 0)
    }
}
__global__ void k_finish(float* __restrict__ oc, float* __restrict__ ob) {
    int i = threadIdx.x;
    if (i < N_BATCH) {
        float v = g_loss[i] * (1.0f / ((float)T_SEQ * (float)D_EMBV));
        oc[i] = v; ob[i] = v;
    }
}

// ---------------- launcher --------------------------------------------------------
extern "C" void kernel_launch(void* const* d_in, const int* in_sizes, int n_in,
                              void* d_out, int out_size) {
    const float* z_e    = (const float*)d_in[0];
    const float* cb     = (const float*)d_in[1];
    const float* w_down = (const float*)d_in[2];
    const float* w_up   = (const float*)d_in[3];

    float* out     = (float*)d_out;
    float* zq      = out;
    float* zed     = out + (size_t)BT_TOK * D_INV;
    float* codef   = out + (size_t)BT_TOK * (D_INV + D_EMBV);
    float* lcommit = codef + BT_TOK;
    float* lcb     = lcommit + N_BATCH;

    cudaFuncSetAttribute(k_down, cudaFuncAttributeMaxDynamicSharedMemorySize, KD_SMEM);
    cudaFuncSetAttribute(k_dist, cudaFuncAttributeMaxDynamicSharedMemorySize, DS_SMEM);

    // k_dist stays the 4th launch for ncu visibility
    k_prep<<<(D_EMBV * D_INV + K_CODES * D_EMBV + 255) / 256, 256>>>(w_down, cb);
    k_c2<<<(K_CODES + 255) / 256, 256>>>(cb);
    k_down<<<dim3(BT_TOK / 128, 2), 512, KD_SMEM>>>(z_e, zed);
    k_dist<<<BT_TOK / 128, 512, DS_SMEM>>>(zed, codef);
    k_cbup<<<dim3(K_CODES / 64, D_INV / 64), 256>>>(cb, w_up);
    k_zero<<<1, 32>>>();
    k_fix<<<512, 256>>>(zed, cb, codef);
    k_gather<<<(BT_TOK * 128) / 256, 256>>>(zq);
    k_loss<<<BT_TOK / 8, 256>>>(zed, cb);
    k_finish<<<1, 32>>>(lcommit, lcb);
}